// round 2
// baseline (speedup 1.0000x reference)
#include <cuda_runtime.h>
#include <cuda_bf16.h>

#define N_NODES 10000
#define E_EDGES 640000
#define IN_CH   512
#define OUT_CH  256

// ---------------- device-global scratch (no allocations allowed) ----------------
__device__ int   g_deg[N_NODES];
__device__ int   g_rowptr[N_NODES + 1];
__device__ int   g_cursor[N_NODES];
__device__ float g_dinv[N_NODES];
__device__ int   g_col[E_EDGES];
__device__ float g_norm[E_EDGES];
__device__ float g_bufB[N_NODES * OUT_CH];
__device__ float g_bufC[N_NODES * OUT_CH];

// ---------------- CSR construction ----------------
__global__ void k_zero_deg() {
    int i = blockIdx.x * blockDim.x + threadIdx.x;
    if (i < N_NODES) g_deg[i] = 0;
}

// edge_index delivered as int32: ei[0..E) = row, ei[E..2E) = col
__global__ void k_count(const int* __restrict__ ei) {
    int e = blockIdx.x * blockDim.x + threadIdx.x;
    if (e < E_EDGES) {
        int r = ei[e];
        r = min(max(r, 0), N_NODES - 1);   // defensive clamp
        atomicAdd(&g_deg[r], 1);
    }
}

// single-block exclusive scan over deg -> rowptr (+ cursor copy, + dinv)
__global__ void k_scan() {
    __shared__ int s[1024];
    __shared__ int carry_s;
    if (threadIdx.x == 0) carry_s = 0;
    __syncthreads();
    for (int base = 0; base < N_NODES; base += 1024) {
        int i = base + threadIdx.x;
        int v = (i < N_NODES) ? g_deg[i] : 0;
        s[threadIdx.x] = v;
        __syncthreads();
        // Hillis-Steele inclusive scan
        #pragma unroll
        for (int off = 1; off < 1024; off <<= 1) {
            int t = (threadIdx.x >= off) ? s[threadIdx.x - off] : 0;
            __syncthreads();
            s[threadIdx.x] += t;
            __syncthreads();
        }
        int incl = s[threadIdx.x];
        int c = carry_s;
        if (i < N_NODES) {
            int excl = c + incl - v;
            g_rowptr[i] = excl;
            g_cursor[i] = excl;
            g_dinv[i]   = (v > 0) ? rsqrtf((float)v) : 0.0f;
        }
        __syncthreads();
        if (threadIdx.x == 1023) carry_s = c + s[1023];
        __syncthreads();
    }
    if (threadIdx.x == 0) g_rowptr[N_NODES] = carry_s;
}

__global__ void k_fill(const int* __restrict__ ei) {
    int e = blockIdx.x * blockDim.x + threadIdx.x;
    if (e < E_EDGES) {
        int r = ei[e];
        int c = ei[E_EDGES + e];
        r = min(max(r, 0), N_NODES - 1);   // defensive clamp
        c = min(max(c, 0), N_NODES - 1);
        float nm = g_dinv[r] * g_dinv[c];
        int pos = atomicAdd(&g_cursor[r], 1);
        if (pos >= 0 && pos < E_EDGES) {
            g_col[pos]  = c;
            g_norm[pos] = nm;
        }
    }
}

// ---------------- GEMM: out[n,o] = sum_k x[n,k]*W[o,k] + b[o] ----------------
// BM=128, BN=64, BK=16, 256 threads, each computes 8x4.
#define BM 128
#define BN 64
#define BK 16

__global__ __launch_bounds__(256) void k_gemm(const float* __restrict__ x,
                                              const float* __restrict__ w,
                                              const float* __restrict__ b,
                                              float* __restrict__ out) {
    __shared__ float As[BK][BM];      // transposed: As[k][m]
    __shared__ float Bs[BK][BN];      // transposed: Bs[k][o]

    const int bm  = blockIdx.x * BM;
    const int bn  = blockIdx.y * BN;
    const int tid = threadIdx.x;

    const int ty = tid >> 4;          // 0..15 -> 8 rows each
    const int tx = tid & 15;          // 0..15 -> 4 cols each

    const int a_row = tid >> 2;       // 0..63
    const int a_k4  = (tid & 3) * 4;  // 0,4,8,12
    const int b_o  = tid >> 2;        // 0..63
    const int b_k4 = (tid & 3) * 4;

    float acc[8][4];
    #pragma unroll
    for (int i = 0; i < 8; i++)
        #pragma unroll
        for (int j = 0; j < 4; j++) acc[i][j] = 0.0f;

    for (int k0 = 0; k0 < IN_CH; k0 += BK) {
        // load A tile (2 float4s per thread)
        #pragma unroll
        for (int it = 0; it < 2; it++) {
            int m = bm + a_row + it * 64;
            float4 v;
            if (m < N_NODES) {
                v = *reinterpret_cast<const float4*>(&x[(long)m * IN_CH + k0 + a_k4]);
            } else {
                v = make_float4(0.f, 0.f, 0.f, 0.f);
            }
            As[a_k4 + 0][a_row + it * 64] = v.x;
            As[a_k4 + 1][a_row + it * 64] = v.y;
            As[a_k4 + 2][a_row + it * 64] = v.z;
            As[a_k4 + 3][a_row + it * 64] = v.w;
        }
        // load B tile (1 float4 per thread)
        {
            float4 v = *reinterpret_cast<const float4*>(&w[(long)(bn + b_o) * IN_CH + k0 + b_k4]);
            Bs[b_k4 + 0][b_o] = v.x;
            Bs[b_k4 + 1][b_o] = v.y;
            Bs[b_k4 + 2][b_o] = v.z;
            Bs[b_k4 + 3][b_o] = v.w;
        }
        __syncthreads();

        #pragma unroll
        for (int kk = 0; kk < BK; kk++) {
            float a[8], bb[4];
            #pragma unroll
            for (int i = 0; i < 8; i++) a[i] = As[kk][ty * 8 + i];
            #pragma unroll
            for (int j = 0; j < 4; j++) bb[j] = Bs[kk][tx * 4 + j];
            #pragma unroll
            for (int i = 0; i < 8; i++)
                #pragma unroll
                for (int j = 0; j < 4; j++) acc[i][j] += a[i] * bb[j];
        }
        __syncthreads();
    }

    #pragma unroll
    for (int j = 0; j < 4; j++) {
        float bias = b[bn + tx * 4 + j];
        #pragma unroll
        for (int i = 0; i < 8; i++) {
            int m = bm + ty * 8 + i;
            if (m < N_NODES) {
                out[(long)m * OUT_CH + bn + tx * 4 + j] = acc[i][j] + bias;
            }
        }
    }
}

// ---------------- SpMM gather (one row per block, one channel per thread) ----------------
// out[row,c] = base ? base[row,c] + w[widx] * acc : acc
// acc = sum over CSR edges of row: norm[e] * h[col[e], c]
__global__ __launch_bounds__(256) void k_spmm(const float* __restrict__ h,
                                              const float* __restrict__ base,
                                              const float* __restrict__ wptr,
                                              int widx,
                                              float* __restrict__ out) {
    __shared__ int   scol[128];
    __shared__ float snorm[128];

    const int row = blockIdx.x;
    const int c   = threadIdx.x;
    const int s   = g_rowptr[row];
    const int e   = g_rowptr[row + 1];

    float acc = 0.0f;
    for (int bs = s; bs < e; bs += 128) {
        int cnt = min(128, e - bs);
        if (threadIdx.x < cnt) {
            scol[threadIdx.x]  = g_col[bs + threadIdx.x];
            snorm[threadIdx.x] = g_norm[bs + threadIdx.x];
        }
        __syncthreads();
        int j = 0;
        // manual 4x unroll for MLP on the L2-resident gathers
        for (; j + 4 <= cnt; j += 4) {
            float v0 = h[(long)scol[j + 0] * OUT_CH + c];
            float v1 = h[(long)scol[j + 1] * OUT_CH + c];
            float v2 = h[(long)scol[j + 2] * OUT_CH + c];
            float v3 = h[(long)scol[j + 3] * OUT_CH + c];
            acc += snorm[j + 0] * v0;
            acc += snorm[j + 1] * v1;
            acc += snorm[j + 2] * v2;
            acc += snorm[j + 3] * v3;
        }
        for (; j < cnt; j++) {
            acc += snorm[j] * h[(long)scol[j] * OUT_CH + c];
        }
        __syncthreads();
    }

    float o;
    if (base != nullptr) {
        o = base[(long)row * OUT_CH + c] + wptr[widx] * acc;
    } else {
        o = acc;
    }
    out[(long)row * OUT_CH + c] = o;
}

// ---------------- launch ----------------
extern "C" void kernel_launch(void* const* d_in, const int* in_sizes, int n_in,
                              void* d_out, int out_size) {
    const float* x   = (const float*)d_in[0];
    const int*   ei  = (const int*)d_in[1];      // edge_index delivered as int32
    const float* lw  = (const float*)d_in[2];
    const float* lb  = (const float*)d_in[3];
    const float* wts = (const float*)d_in[4];
    float*       out = (float*)d_out;

    float* bufB;
    float* bufC;
    cudaGetSymbolAddress((void**)&bufB, g_bufB);
    cudaGetSymbolAddress((void**)&bufC, g_bufC);

    // CSR build
    k_zero_deg<<<(N_NODES + 255) / 256, 256>>>();
    k_count<<<(E_EDGES + 255) / 256, 256>>>(ei);
    k_scan<<<1, 1024>>>();
    k_fill<<<(E_EDGES + 255) / 256, 256>>>(ei);

    // out0 = x @ W^T + b   -> d_out
    dim3 ggrid((N_NODES + BM - 1) / BM, OUT_CH / BN);
    k_gemm<<<ggrid, 256>>>(x, lw, lb, out);

    // k=0: bufB = out0 + w0 * A(out0)
    k_spmm<<<N_NODES, 256>>>(out, out, wts, 0, bufB);
    // k=1: bufC = A(bufB)
    k_spmm<<<N_NODES, 256>>>(bufB, nullptr, wts, 0, bufC);
    //      d_out = bufB + w1 * A(bufC)
    k_spmm<<<N_NODES, 256>>>(bufC, bufB, wts, 1, out);
}

// round 3
// speedup vs baseline: 1.2013x; 1.2013x over previous
#include <cuda_runtime.h>
#include <cuda_bf16.h>

#define N_NODES 10000
#define E_EDGES 640000
#define IN_CH   512
#define OUT_CH  256

// ---------------- device-global scratch (no allocations allowed) ----------------
__device__ int   g_deg[N_NODES];
__device__ int   g_rowptr[N_NODES + 1];
__device__ int   g_cursor[N_NODES];
__device__ float g_dinv[N_NODES];
__device__ int   g_col[E_EDGES];
__device__ float g_norm[E_EDGES];
__device__ float g_bufB[N_NODES * OUT_CH];
__device__ float g_bufC[N_NODES * OUT_CH];

// ---------------- CSR construction ----------------
__global__ void k_zero_deg() {
    int i = blockIdx.x * blockDim.x + threadIdx.x;
    if (i < N_NODES) g_deg[i] = 0;
}

// edge_index delivered as int32: ei[0..E) = row, ei[E..2E) = col
__global__ void k_count(const int* __restrict__ ei) {
    int e = blockIdx.x * blockDim.x + threadIdx.x;
    if (e < E_EDGES) {
        int r = ei[e];
        r = min(max(r, 0), N_NODES - 1);
        atomicAdd(&g_deg[r], 1);
    }
}

// 1-block register-blocked scan: 1024 threads x 10 elements each (10240 >= N)
#define SCAN_PER 10
__global__ __launch_bounds__(1024) void k_scan() {
    const int tid  = threadIdx.x;
    const int lane = tid & 31;
    const int wid  = tid >> 5;
    const int base = tid * SCAN_PER;

    int excl_local[SCAN_PER];
    int sum = 0;
    #pragma unroll
    for (int q = 0; q < SCAN_PER; q++) {
        int i = base + q;
        int v = (i < N_NODES) ? g_deg[i] : 0;
        excl_local[q] = sum;
        sum += v;
    }

    // inclusive warp scan of per-thread sums
    int inc = sum;
    #pragma unroll
    for (int off = 1; off < 32; off <<= 1) {
        int t = __shfl_up_sync(0xFFFFFFFFu, inc, off);
        if (lane >= off) inc += t;
    }

    __shared__ int wsum[32];
    if (lane == 31) wsum[wid] = inc;
    __syncthreads();
    if (wid == 0) {
        int v = wsum[lane];
        int wi = v;
        #pragma unroll
        for (int off = 1; off < 32; off <<= 1) {
            int t = __shfl_up_sync(0xFFFFFFFFu, wi, off);
            if (lane >= off) wi += t;
        }
        wsum[lane] = wi - v;   // exclusive warp offsets
    }
    __syncthreads();

    const int offset = wsum[wid] + (inc - sum);   // exclusive prefix for this thread

    #pragma unroll
    for (int q = 0; q < SCAN_PER; q++) {
        int i = base + q;
        if (i < N_NODES) {
            int excl = offset + excl_local[q];
            g_rowptr[i] = excl;
            g_cursor[i] = excl;
            int d = g_deg[i];
            g_dinv[i] = (d > 0) ? rsqrtf((float)d) : 0.0f;
        }
    }
    if (tid == 1023) g_rowptr[N_NODES] = offset + sum;
}

__global__ void k_fill(const int* __restrict__ ei) {
    int e = blockIdx.x * blockDim.x + threadIdx.x;
    if (e < E_EDGES) {
        int r = ei[e];
        int c = ei[E_EDGES + e];
        r = min(max(r, 0), N_NODES - 1);
        c = min(max(c, 0), N_NODES - 1);
        float nm = g_dinv[r] * g_dinv[c];
        int pos = atomicAdd(&g_cursor[r], 1);
        if (pos >= 0 && pos < E_EDGES) {
            g_col[pos]  = c;
            g_norm[pos] = nm;
        }
    }
}

// ---------------- GEMM: out[n,o] = sum_k x[n,k]*W[o,k] + b[o] ----------------
// 128x128 tile, BK=16, 256 threads, each computes 8x8.
#define BM 128
#define BN 128
#define BK 16

__global__ __launch_bounds__(256) void k_gemm(const float* __restrict__ x,
                                              const float* __restrict__ w,
                                              const float* __restrict__ b,
                                              float* __restrict__ out) {
    __shared__ float As[BK][BM];   // As[k][m]
    __shared__ float Bs[BK][BN];   // Bs[k][o]

    const int bm  = blockIdx.x * BM;
    const int bn  = blockIdx.y * BN;
    const int tid = threadIdx.x;

    const int ty = tid >> 4;            // 0..15
    const int tx = tid & 15;            // 0..15
    const int m0 = ty * 8;
    const int n0 = tx * 8;

    // loader mapping: 512 float4 slots per tile, 2 per thread
    // slot -> row = slot/4 (0..127), k4 = (slot%4)*4
    float acc[8][8];
    #pragma unroll
    for (int i = 0; i < 8; i++)
        #pragma unroll
        for (int j = 0; j < 8; j++) acc[i][j] = 0.0f;

    for (int k0 = 0; k0 < IN_CH; k0 += BK) {
        #pragma unroll
        for (int it = 0; it < 2; it++) {
            int slot = tid + it * 256;
            int row  = slot >> 2;
            int k4   = (slot & 3) * 4;
            // A tile
            {
                int m = bm + row;
                float4 v = make_float4(0.f, 0.f, 0.f, 0.f);
                if (m < N_NODES)
                    v = *reinterpret_cast<const float4*>(&x[(long)m * IN_CH + k0 + k4]);
                As[k4 + 0][row] = v.x;
                As[k4 + 1][row] = v.y;
                As[k4 + 2][row] = v.z;
                As[k4 + 3][row] = v.w;
            }
            // B tile (bn+row < 256 always, grid exact in N)
            {
                float4 v = *reinterpret_cast<const float4*>(&w[(long)(bn + row) * IN_CH + k0 + k4]);
                Bs[k4 + 0][row] = v.x;
                Bs[k4 + 1][row] = v.y;
                Bs[k4 + 2][row] = v.z;
                Bs[k4 + 3][row] = v.w;
            }
        }
        __syncthreads();

        #pragma unroll
        for (int kk = 0; kk < BK; kk++) {
            float a[8], bb[8];
            #pragma unroll
            for (int i = 0; i < 8; i += 4) {
                float4 v = *reinterpret_cast<const float4*>(&As[kk][m0 + i]);
                a[i] = v.x; a[i + 1] = v.y; a[i + 2] = v.z; a[i + 3] = v.w;
            }
            #pragma unroll
            for (int j = 0; j < 8; j += 4) {
                float4 v = *reinterpret_cast<const float4*>(&Bs[kk][n0 + j]);
                bb[j] = v.x; bb[j + 1] = v.y; bb[j + 2] = v.z; bb[j + 3] = v.w;
            }
            #pragma unroll
            for (int i = 0; i < 8; i++)
                #pragma unroll
                for (int j = 0; j < 8; j++) acc[i][j] += a[i] * bb[j];
        }
        __syncthreads();
    }

    float bias[8];
    #pragma unroll
    for (int j = 0; j < 8; j++) bias[j] = b[bn + n0 + j];

    #pragma unroll
    for (int i = 0; i < 8; i++) {
        int m = bm + m0 + i;
        if (m < N_NODES) {
            #pragma unroll
            for (int j = 0; j < 8; j += 4) {
                float4 v;
                v.x = acc[i][j + 0] + bias[j + 0];
                v.y = acc[i][j + 1] + bias[j + 1];
                v.z = acc[i][j + 2] + bias[j + 2];
                v.w = acc[i][j + 3] + bias[j + 3];
                *reinterpret_cast<float4*>(&out[(long)m * OUT_CH + bn + n0 + j]) = v;
            }
        }
    }
}

// ---------------- SpMM gather: one row per 64-thread block, float4 channels --------
// out[row,:] = base ? base[row,:] + w[widx]*acc : acc
__global__ __launch_bounds__(64) void k_spmm(const float4* __restrict__ h4,
                                             const float4* __restrict__ base4,
                                             const float* __restrict__ wptr,
                                             int widx,
                                             float4* __restrict__ out4) {
    __shared__ int   scol[256];
    __shared__ float snorm[256];

    const int row = blockIdx.x;
    const int tid = threadIdx.x;        // 0..63, owns 4 channels
    const int s   = g_rowptr[row];
    const int e   = g_rowptr[row + 1];

    float4 acc = make_float4(0.f, 0.f, 0.f, 0.f);

    for (int bs = s; bs < e; bs += 256) {
        int cnt = min(256, e - bs);
        for (int j = tid; j < cnt; j += 64) {
            scol[j]  = g_col[bs + j];
            snorm[j] = g_norm[bs + j];
        }
        __syncthreads();
        int j = 0;
        for (; j + 4 <= cnt; j += 4) {
            int   c0 = scol[j + 0], c1 = scol[j + 1], c2 = scol[j + 2], c3 = scol[j + 3];
            float n0 = snorm[j + 0], n1 = snorm[j + 1], n2 = snorm[j + 2], n3 = snorm[j + 3];
            float4 v0 = h4[(long)c0 * 64 + tid];
            float4 v1 = h4[(long)c1 * 64 + tid];
            float4 v2 = h4[(long)c2 * 64 + tid];
            float4 v3 = h4[(long)c3 * 64 + tid];
            acc.x += n0 * v0.x; acc.y += n0 * v0.y; acc.z += n0 * v0.z; acc.w += n0 * v0.w;
            acc.x += n1 * v1.x; acc.y += n1 * v1.y; acc.z += n1 * v1.z; acc.w += n1 * v1.w;
            acc.x += n2 * v2.x; acc.y += n2 * v2.y; acc.z += n2 * v2.z; acc.w += n2 * v2.w;
            acc.x += n3 * v3.x; acc.y += n3 * v3.y; acc.z += n3 * v3.z; acc.w += n3 * v3.w;
        }
        for (; j < cnt; j++) {
            float n = snorm[j];
            float4 v = h4[(long)scol[j] * 64 + tid];
            acc.x += n * v.x; acc.y += n * v.y; acc.z += n * v.z; acc.w += n * v.w;
        }
        __syncthreads();
    }

    float4 o;
    if (base4 != nullptr) {
        float wk = wptr[widx];
        float4 bv = base4[(long)row * 64 + tid];
        o.x = bv.x + wk * acc.x;
        o.y = bv.y + wk * acc.y;
        o.z = bv.z + wk * acc.z;
        o.w = bv.w + wk * acc.w;
    } else {
        o = acc;
    }
    out4[(long)row * 64 + tid] = o;
}

// ---------------- launch ----------------
extern "C" void kernel_launch(void* const* d_in, const int* in_sizes, int n_in,
                              void* d_out, int out_size) {
    const float* x   = (const float*)d_in[0];
    const int*   ei  = (const int*)d_in[1];      // edge_index delivered as int32
    const float* lw  = (const float*)d_in[2];
    const float* lb  = (const float*)d_in[3];
    const float* wts = (const float*)d_in[4];
    float*       out = (float*)d_out;

    float* bufB;
    float* bufC;
    cudaGetSymbolAddress((void**)&bufB, g_bufB);
    cudaGetSymbolAddress((void**)&bufC, g_bufC);

    // CSR build
    k_zero_deg<<<(N_NODES + 255) / 256, 256>>>();
    k_count<<<(E_EDGES + 255) / 256, 256>>>(ei);
    k_scan<<<1, 1024>>>();
    k_fill<<<(E_EDGES + 255) / 256, 256>>>(ei);

    // out0 = x @ W^T + b   -> d_out
    dim3 ggrid((N_NODES + BM - 1) / BM, OUT_CH / BN);
    k_gemm<<<ggrid, 256>>>(x, lw, lb, out);

    // k=0: bufB = out0 + w0 * A(out0)
    k_spmm<<<N_NODES, 64>>>((const float4*)out, (const float4*)out, wts, 0, (float4*)bufB);
    // k=1: bufC = A(bufB)
    k_spmm<<<N_NODES, 64>>>((const float4*)bufB, nullptr, wts, 0, (float4*)bufC);
    //      d_out = bufB + w1 * A(bufC)
    k_spmm<<<N_NODES, 64>>>((const float4*)bufC, (const float4*)bufB, wts, 1, (float4*)out);
}

// round 4
// speedup vs baseline: 1.3519x; 1.1253x over previous
#include <cuda_runtime.h>
#include <cuda_fp16.h>

#define N_NODES 10000
#define E_EDGES 640000
#define IN_CH   512
#define OUT_CH  256

// ---------------- device-global scratch (no allocations allowed) ----------------
__device__ int    g_deg[N_NODES];
__device__ int    g_rowptr[N_NODES + 1];
__device__ int    g_cursor[N_NODES];
__device__ float  g_dinv[N_NODES];
__device__ int    g_col[E_EDGES];
__device__ float  g_bufB[N_NODES * OUT_CH];
// fp16 gather mirrors (pre-scaled by dinv[row])
__device__ __half g_m0[N_NODES * OUT_CH];
__device__ __half g_m1[N_NODES * OUT_CH];
__device__ __half g_m2[N_NODES * OUT_CH];

// ---------------- CSR construction ----------------
__global__ void k_zero_deg() {
    int i = blockIdx.x * blockDim.x + threadIdx.x;
    if (i < N_NODES) g_deg[i] = 0;
}

// edge_index delivered as int32: ei[0..E) = row, ei[E..2E) = col
__global__ void k_count(const int* __restrict__ ei) {
    int e = blockIdx.x * blockDim.x + threadIdx.x;
    if (e < E_EDGES) {
        int r = ei[e];
        r = min(max(r, 0), N_NODES - 1);
        atomicAdd(&g_deg[r], 1);
    }
}

// 1-block register-blocked scan: 1024 threads x 10 elements each (10240 >= N)
#define SCAN_PER 10
__global__ __launch_bounds__(1024) void k_scan() {
    const int tid  = threadIdx.x;
    const int lane = tid & 31;
    const int wid  = tid >> 5;
    const int base = tid * SCAN_PER;

    int excl_local[SCAN_PER];
    int sum = 0;
    #pragma unroll
    for (int q = 0; q < SCAN_PER; q++) {
        int i = base + q;
        int v = (i < N_NODES) ? g_deg[i] : 0;
        excl_local[q] = sum;
        sum += v;
    }

    int inc = sum;
    #pragma unroll
    for (int off = 1; off < 32; off <<= 1) {
        int t = __shfl_up_sync(0xFFFFFFFFu, inc, off);
        if (lane >= off) inc += t;
    }

    __shared__ int wsum[32];
    if (lane == 31) wsum[wid] = inc;
    __syncthreads();
    if (wid == 0) {
        int v = wsum[lane];
        int wi = v;
        #pragma unroll
        for (int off = 1; off < 32; off <<= 1) {
            int t = __shfl_up_sync(0xFFFFFFFFu, wi, off);
            if (lane >= off) wi += t;
        }
        wsum[lane] = wi - v;
    }
    __syncthreads();

    const int offset = wsum[wid] + (inc - sum);

    #pragma unroll
    for (int q = 0; q < SCAN_PER; q++) {
        int i = base + q;
        if (i < N_NODES) {
            int excl = offset + excl_local[q];
            g_rowptr[i] = excl;
            g_cursor[i] = excl;
            int d = g_deg[i];
            g_dinv[i] = (d > 0) ? rsqrtf((float)d) : 0.0f;
        }
    }
    if (tid == 1023) g_rowptr[N_NODES] = offset + sum;
}

__global__ void k_fill(const int* __restrict__ ei) {
    int e = blockIdx.x * blockDim.x + threadIdx.x;
    if (e < E_EDGES) {
        int r = ei[e];
        int c = ei[E_EDGES + e];
        r = min(max(r, 0), N_NODES - 1);
        c = min(max(c, 0), N_NODES - 1);
        int pos = atomicAdd(&g_cursor[r], 1);
        if (pos >= 0 && pos < E_EDGES) g_col[pos] = c;
    }
}

// ---------------- GEMM: out[n,o] = sum_k x[n,k]*W[o,k] + b[o] ----------------
// 128x128 tile, BK=16, 256 threads, each computes 8x8.
// Epilogue also writes fp16 mirror m0 = fp16(out * dinv[row]).
#define BM 128
#define BN 128
#define BK 16

__global__ __launch_bounds__(256) void k_gemm(const float* __restrict__ x,
                                              const float* __restrict__ w,
                                              const float* __restrict__ b,
                                              float* __restrict__ out,
                                              __half* __restrict__ mir) {
    __shared__ float As[BK][BM];
    __shared__ float Bs[BK][BN];

    const int bm  = blockIdx.x * BM;
    const int bn  = blockIdx.y * BN;
    const int tid = threadIdx.x;

    const int ty = tid >> 4;
    const int tx = tid & 15;
    const int m0 = ty * 8;
    const int n0 = tx * 8;

    float acc[8][8];
    #pragma unroll
    for (int i = 0; i < 8; i++)
        #pragma unroll
        for (int j = 0; j < 8; j++) acc[i][j] = 0.0f;

    for (int k0 = 0; k0 < IN_CH; k0 += BK) {
        #pragma unroll
        for (int it = 0; it < 2; it++) {
            int slot = tid + it * 256;
            int row  = slot >> 2;
            int k4   = (slot & 3) * 4;
            {
                int m = bm + row;
                float4 v = make_float4(0.f, 0.f, 0.f, 0.f);
                if (m < N_NODES)
                    v = *reinterpret_cast<const float4*>(&x[(long)m * IN_CH + k0 + k4]);
                As[k4 + 0][row] = v.x;
                As[k4 + 1][row] = v.y;
                As[k4 + 2][row] = v.z;
                As[k4 + 3][row] = v.w;
            }
            {
                float4 v = *reinterpret_cast<const float4*>(&w[(long)(bn + row) * IN_CH + k0 + k4]);
                Bs[k4 + 0][row] = v.x;
                Bs[k4 + 1][row] = v.y;
                Bs[k4 + 2][row] = v.z;
                Bs[k4 + 3][row] = v.w;
            }
        }
        __syncthreads();

        #pragma unroll
        for (int kk = 0; kk < BK; kk++) {
            float a[8], bb[8];
            #pragma unroll
            for (int i = 0; i < 8; i += 4) {
                float4 v = *reinterpret_cast<const float4*>(&As[kk][m0 + i]);
                a[i] = v.x; a[i + 1] = v.y; a[i + 2] = v.z; a[i + 3] = v.w;
            }
            #pragma unroll
            for (int j = 0; j < 8; j += 4) {
                float4 v = *reinterpret_cast<const float4*>(&Bs[kk][n0 + j]);
                bb[j] = v.x; bb[j + 1] = v.y; bb[j + 2] = v.z; bb[j + 3] = v.w;
            }
            #pragma unroll
            for (int i = 0; i < 8; i++)
                #pragma unroll
                for (int j = 0; j < 8; j++) acc[i][j] += a[i] * bb[j];
        }
        __syncthreads();
    }

    float bias[8];
    #pragma unroll
    for (int j = 0; j < 8; j++) bias[j] = b[bn + n0 + j];

    #pragma unroll
    for (int i = 0; i < 8; i++) {
        int m = bm + m0 + i;
        if (m < N_NODES) {
            float di = g_dinv[m];
            float vals[8];
            #pragma unroll
            for (int j = 0; j < 8; j++) vals[j] = acc[i][j] + bias[j];
            #pragma unroll
            for (int j = 0; j < 8; j += 4) {
                float4 v = make_float4(vals[j], vals[j+1], vals[j+2], vals[j+3]);
                *reinterpret_cast<float4*>(&out[(long)m * OUT_CH + bn + n0 + j]) = v;
            }
            // fp16 mirror, pre-scaled by dinv[m]
            __half h[8];
            #pragma unroll
            for (int j = 0; j < 8; j++) h[j] = __float2half(vals[j] * di);
            *reinterpret_cast<uint4*>(&mir[(long)m * OUT_CH + bn + n0]) =
                *reinterpret_cast<const uint4*>(h);
        }
    }
}

// ---------------- SpMM gather: one row per 64-thread block ----------------
// acc = sum over CSR edges of row of h16[col] (mirror already scaled by dinv[col])
// r   = dinv[row] * acc
// out = base ? base + w[widx]*r : r          (fp32, optional)
// mir = fp16(out * dinv[row])                (optional)
__global__ __launch_bounds__(64) void k_spmm(const uint2* __restrict__ h16,
                                             const float4* __restrict__ base4,
                                             const float* __restrict__ wptr,
                                             int widx,
                                             float4* __restrict__ out4,
                                             uint2* __restrict__ mir) {
    __shared__ int scol[256];

    const int row = blockIdx.x;
    const int tid = threadIdx.x;        // 0..63, owns 4 channels
    const int s   = g_rowptr[row];
    const int e   = g_rowptr[row + 1];

    float4 acc = make_float4(0.f, 0.f, 0.f, 0.f);

    for (int bs = s; bs < e; bs += 256) {
        int cnt = min(256, e - bs);
        for (int j = tid; j < cnt; j += 64) scol[j] = g_col[bs + j];
        __syncthreads();
        int j = 0;
        for (; j + 4 <= cnt; j += 4) {
            int c0 = scol[j + 0], c1 = scol[j + 1], c2 = scol[j + 2], c3 = scol[j + 3];
            uint2 u0 = h16[(long)c0 * 64 + tid];
            uint2 u1 = h16[(long)c1 * 64 + tid];
            uint2 u2 = h16[(long)c2 * 64 + tid];
            uint2 u3 = h16[(long)c3 * 64 + tid];
            float2 a0 = __half22float2(*reinterpret_cast<const __half2*>(&u0.x));
            float2 b0 = __half22float2(*reinterpret_cast<const __half2*>(&u0.y));
            float2 a1 = __half22float2(*reinterpret_cast<const __half2*>(&u1.x));
            float2 b1 = __half22float2(*reinterpret_cast<const __half2*>(&u1.y));
            float2 a2 = __half22float2(*reinterpret_cast<const __half2*>(&u2.x));
            float2 b2 = __half22float2(*reinterpret_cast<const __half2*>(&u2.y));
            float2 a3 = __half22float2(*reinterpret_cast<const __half2*>(&u3.x));
            float2 b3 = __half22float2(*reinterpret_cast<const __half2*>(&u3.y));
            acc.x += a0.x + a1.x + a2.x + a3.x;
            acc.y += a0.y + a1.y + a2.y + a3.y;
            acc.z += b0.x + b1.x + b2.x + b3.x;
            acc.w += b0.y + b1.y + b2.y + b3.y;
        }
        for (; j < cnt; j++) {
            uint2 u = h16[(long)scol[j] * 64 + tid];
            float2 a = __half22float2(*reinterpret_cast<const __half2*>(&u.x));
            float2 b = __half22float2(*reinterpret_cast<const __half2*>(&u.y));
            acc.x += a.x; acc.y += a.y; acc.z += b.x; acc.w += b.y;
        }
        __syncthreads();
    }

    const float di = g_dinv[row];
    float4 r;
    r.x = di * acc.x; r.y = di * acc.y; r.z = di * acc.z; r.w = di * acc.w;

    float4 o;
    if (base4 != nullptr) {
        float wk = wptr[widx];
        float4 bv = base4[(long)row * 64 + tid];
        o.x = bv.x + wk * r.x;
        o.y = bv.y + wk * r.y;
        o.z = bv.z + wk * r.z;
        o.w = bv.w + wk * r.w;
    } else {
        o = r;
    }
    if (out4 != nullptr) out4[(long)row * 64 + tid] = o;
    if (mir != nullptr) {
        __half h[4];
        h[0] = __float2half(o.x * di);
        h[1] = __float2half(o.y * di);
        h[2] = __float2half(o.z * di);
        h[3] = __float2half(o.w * di);
        mir[(long)row * 64 + tid] = *reinterpret_cast<const uint2*>(h);
    }
}

// ---------------- launch ----------------
extern "C" void kernel_launch(void* const* d_in, const int* in_sizes, int n_in,
                              void* d_out, int out_size) {
    const float* x   = (const float*)d_in[0];
    const int*   ei  = (const int*)d_in[1];      // edge_index delivered as int32
    const float* lw  = (const float*)d_in[2];
    const float* lb  = (const float*)d_in[3];
    const float* wts = (const float*)d_in[4];
    float*       out = (float*)d_out;

    float* bufB;  __half *m0, *m1, *m2;
    cudaGetSymbolAddress((void**)&bufB, g_bufB);
    cudaGetSymbolAddress((void**)&m0, g_m0);
    cudaGetSymbolAddress((void**)&m1, g_m1);
    cudaGetSymbolAddress((void**)&m2, g_m2);

    // CSR build (scan computes dinv before GEMM epilogue needs it)
    k_zero_deg<<<(N_NODES + 255) / 256, 256>>>();
    k_count<<<(E_EDGES + 255) / 256, 256>>>(ei);
    k_scan<<<1, 1024>>>();

    // out0 = x @ W^T + b -> d_out ; m0 = fp16(out0 * dinv)
    dim3 ggrid((N_NODES + BM - 1) / BM, OUT_CH / BN);
    k_gemm<<<ggrid, 256>>>(x, lw, lb, out, m0);

    k_fill<<<(E_EDGES + 255) / 256, 256>>>(ei);

    // k=0: bufB = out0 + w0 * A(out0); m1 = fp16(bufB * dinv)
    k_spmm<<<N_NODES, 64>>>((const uint2*)m0, (const float4*)out, wts, 0,
                            (float4*)bufB, (uint2*)m1);
    // k=1 hop 1: m2 = fp16(A(bufB) * dinv)   (fp32 output not needed)
    k_spmm<<<N_NODES, 64>>>((const uint2*)m1, nullptr, wts, 0,
                            nullptr, (uint2*)m2);
    // k=1 hop 2: d_out = bufB + w1 * A(prev)
    k_spmm<<<N_NODES, 64>>>((const uint2*)m2, (const float4*)bufB, wts, 1,
                            (float4*)out, nullptr);
}

// round 5
// speedup vs baseline: 1.4451x; 1.0689x over previous
#include <cuda_runtime.h>
#include <cuda_fp16.h>
#include <cuda_bf16.h>

#define N_NODES 10000
#define E_EDGES 640000
#define IN_CH   512
#define OUT_CH  256

// ---------------- device-global scratch (no allocations allowed) ----------------
__device__ int    g_deg[N_NODES];
__device__ int    g_rowptr[N_NODES + 1];
__device__ int    g_cursor[N_NODES];
__device__ float  g_dinv[N_NODES];
__device__ int    g_col[E_EDGES];
__device__ float  g_bufB[N_NODES * OUT_CH];
// fp16 gather mirrors (pre-scaled by dinv[row])
__device__ __half g_m0[N_NODES * OUT_CH];
__device__ __half g_m1[N_NODES * OUT_CH];
__device__ __half g_m2[N_NODES * OUT_CH];
// bf16x3 split operands for the tensor-core GEMM
__device__ __nv_bfloat16 g_xh[N_NODES * IN_CH];
__device__ __nv_bfloat16 g_xl[N_NODES * IN_CH];
__device__ __nv_bfloat16 g_wh[OUT_CH * IN_CH];
__device__ __nv_bfloat16 g_wl[OUT_CH * IN_CH];

// ---------------- CSR construction ----------------
__global__ void k_zero_deg() {
    int i = blockIdx.x * blockDim.x + threadIdx.x;
    if (i < N_NODES) g_deg[i] = 0;
}

// edge_index delivered as int32: ei[0..E) = row, ei[E..2E) = col
__global__ void k_count(const int* __restrict__ ei) {
    int e = blockIdx.x * blockDim.x + threadIdx.x;
    if (e < E_EDGES) {
        int r = ei[e];
        r = min(max(r, 0), N_NODES - 1);
        atomicAdd(&g_deg[r], 1);
    }
}

// 1-block register-blocked scan: 1024 threads x 10 elements each (10240 >= N)
#define SCAN_PER 10
__global__ __launch_bounds__(1024) void k_scan() {
    const int tid  = threadIdx.x;
    const int lane = tid & 31;
    const int wid  = tid >> 5;
    const int base = tid * SCAN_PER;

    int excl_local[SCAN_PER];
    int sum = 0;
    #pragma unroll
    for (int q = 0; q < SCAN_PER; q++) {
        int i = base + q;
        int v = (i < N_NODES) ? g_deg[i] : 0;
        excl_local[q] = sum;
        sum += v;
    }

    int inc = sum;
    #pragma unroll
    for (int off = 1; off < 32; off <<= 1) {
        int t = __shfl_up_sync(0xFFFFFFFFu, inc, off);
        if (lane >= off) inc += t;
    }

    __shared__ int wsum[32];
    if (lane == 31) wsum[wid] = inc;
    __syncthreads();
    if (wid == 0) {
        int v = wsum[lane];
        int wi = v;
        #pragma unroll
        for (int off = 1; off < 32; off <<= 1) {
            int t = __shfl_up_sync(0xFFFFFFFFu, wi, off);
            if (lane >= off) wi += t;
        }
        wsum[lane] = wi - v;
    }
    __syncthreads();

    const int offset = wsum[wid] + (inc - sum);

    #pragma unroll
    for (int q = 0; q < SCAN_PER; q++) {
        int i = base + q;
        if (i < N_NODES) {
            int excl = offset + excl_local[q];
            g_rowptr[i] = excl;
            g_cursor[i] = excl;
            int d = g_deg[i];
            g_dinv[i] = (d > 0) ? rsqrtf((float)d) : 0.0f;
        }
    }
    if (tid == 1023) g_rowptr[N_NODES] = offset + sum;
}

__global__ void k_fill(const int* __restrict__ ei) {
    int e = blockIdx.x * blockDim.x + threadIdx.x;
    if (e < E_EDGES) {
        int r = ei[e];
        int c = ei[E_EDGES + e];
        r = min(max(r, 0), N_NODES - 1);
        c = min(max(c, 0), N_NODES - 1);
        int pos = atomicAdd(&g_cursor[r], 1);
        if (pos >= 0 && pos < E_EDGES) g_col[pos] = c;
    }
}

// ---------------- bf16 hi/lo split conversion ----------------
__global__ void k_cvt(const float4* __restrict__ src,
                      uint2* __restrict__ hi, uint2* __restrict__ lo, int n4) {
    int i = blockIdx.x * blockDim.x + threadIdx.x;
    if (i < n4) {
        float4 v = src[i];
        __nv_bfloat16 h[4], l[4];
        h[0] = __float2bfloat16_rn(v.x); l[0] = __float2bfloat16_rn(v.x - __bfloat162float(h[0]));
        h[1] = __float2bfloat16_rn(v.y); l[1] = __float2bfloat16_rn(v.y - __bfloat162float(h[1]));
        h[2] = __float2bfloat16_rn(v.z); l[2] = __float2bfloat16_rn(v.z - __bfloat162float(h[2]));
        h[3] = __float2bfloat16_rn(v.w); l[3] = __float2bfloat16_rn(v.w - __bfloat162float(h[3]));
        hi[i] = *reinterpret_cast<const uint2*>(h);
        lo[i] = *reinterpret_cast<const uint2*>(l);
    }
}

// ---------------- Tensor-core GEMM (bf16x3, fp32 accum) ----------------
// out[n,o] = sum_k x[n,k]*W[o,k] + b[o];  also mir = fp16(out*dinv[n]).
// CTA tile 128x64, 4 warps, warp tile 64x32, mma.m16n8k16.
// Segments: (xh,wh), (xl,wh), (xh,wl).
#define GBM 128
#define GBN 64
#define SMSTRIDE 24   // bf16 elements per smem row (16 data + 8 pad) -> conflict-free

__global__ __launch_bounds__(128) void k_gemm_mma(const float* __restrict__ bias,
                                                  float* __restrict__ out,
                                                  __half* __restrict__ mir) {
    __shared__ __nv_bfloat16 As[2][GBM][SMSTRIDE];
    __shared__ __nv_bfloat16 Bs[2][GBN][SMSTRIDE];

    const int tid  = threadIdx.x;
    const int wid  = tid >> 5;
    const int lane = tid & 31;
    const int bm   = blockIdx.x * GBM;
    const int bn   = blockIdx.y * GBN;
    const int wm   = (wid & 1) * 64;    // warp M offset
    const int wn   = (wid >> 1) * 32;   // warp N offset
    const int q    = lane >> 2;         // 0..7
    const int s    = lane & 3;          // 0..3

    const __nv_bfloat16* xh = g_xh;
    const __nv_bfloat16* xl = g_xl;
    const __nv_bfloat16* wh = g_wh;
    const __nv_bfloat16* wl = g_wl;

    float d[4][4][4];
    #pragma unroll
    for (int mi = 0; mi < 4; mi++)
        #pragma unroll
        for (int ni = 0; ni < 4; ni++)
            #pragma unroll
            for (int r = 0; r < 4; r++) d[mi][ni][r] = 0.0f;

    uint4 pa0, pa1, pb0, pb1;
    const uint4 z4 = make_uint4(0u, 0u, 0u, 0u);

    // ---- prefetch chunk (seg, k0) into registers ----
    #define PREFETCH(ch)                                                         \
    {                                                                            \
        int seg_ = (ch) >> 5;                                                    \
        int k0_  = ((ch) & 31) * 16;                                             \
        const __nv_bfloat16* A_ = (seg_ == 1) ? xl : xh;                         \
        const __nv_bfloat16* B_ = (seg_ == 2) ? wl : wh;                         \
        int m_ = bm + tid;                                                       \
        if (m_ < N_NODES) {                                                      \
            const uint4* p_ = reinterpret_cast<const uint4*>(&A_[(long)m_ * IN_CH + k0_]); \
            pa0 = p_[0]; pa1 = p_[1];                                            \
        } else { pa0 = z4; pa1 = z4; }                                           \
        if (tid < GBN) {                                                         \
            const uint4* p_ = reinterpret_cast<const uint4*>(&B_[(long)(bn + tid) * IN_CH + k0_]); \
            pb0 = p_[0]; pb1 = p_[1];                                            \
        }                                                                        \
    }

    #define STS(buf)                                                             \
    {                                                                            \
        *reinterpret_cast<uint4*>(&As[buf][tid][0]) = pa0;                       \
        *reinterpret_cast<uint4*>(&As[buf][tid][8]) = pa1;                       \
        if (tid < GBN) {                                                         \
            *reinterpret_cast<uint4*>(&Bs[buf][tid][0]) = pb0;                   \
            *reinterpret_cast<uint4*>(&Bs[buf][tid][8]) = pb1;                   \
        }                                                                        \
    }

    int buf = 0;
    PREFETCH(0);
    STS(0);
    __syncthreads();

    const int NCHUNK = 3 * (IN_CH / 16);   // 96
    for (int ch = 0; ch < NCHUNK; ch++) {
        if (ch + 1 < NCHUNK) PREFETCH(ch + 1);

        // B fragments for this warp's 4 n-tiles
        unsigned bfr[4][2];
        #pragma unroll
        for (int ni = 0; ni < 4; ni++) {
            const __nv_bfloat16* p = &Bs[buf][wn + ni * 8 + q][s * 2];
            bfr[ni][0] = *reinterpret_cast<const unsigned*>(p);
            bfr[ni][1] = *reinterpret_cast<const unsigned*>(p + 8);
        }
        #pragma unroll
        for (int mi = 0; mi < 4; mi++) {
            const __nv_bfloat16* pa = &As[buf][wm + mi * 16 + q][s * 2];
            unsigned a0 = *reinterpret_cast<const unsigned*>(pa);
            unsigned a1 = *reinterpret_cast<const unsigned*>(pa + 8 * SMSTRIDE);
            unsigned a2 = *reinterpret_cast<const unsigned*>(pa + 8);
            unsigned a3 = *reinterpret_cast<const unsigned*>(pa + 8 * SMSTRIDE + 8);
            #pragma unroll
            for (int ni = 0; ni < 4; ni++) {
                asm volatile(
                    "mma.sync.aligned.m16n8k16.row.col.f32.bf16.bf16.f32 "
                    "{%0,%1,%2,%3}, {%4,%5,%6,%7}, {%8,%9}, {%0,%1,%2,%3};"
                    : "+f"(d[mi][ni][0]), "+f"(d[mi][ni][1]),
                      "+f"(d[mi][ni][2]), "+f"(d[mi][ni][3])
                    : "r"(a0), "r"(a1), "r"(a2), "r"(a3),
                      "r"(bfr[ni][0]), "r"(bfr[ni][1]));
            }
        }

        if (ch + 1 < NCHUNK) {
            STS(buf ^ 1);
            __syncthreads();
            buf ^= 1;
        }
    }

    // ---- epilogue: bias, fp32 out, fp16 mirror (scaled by dinv) ----
    float2 bv[4];
    #pragma unroll
    for (int ni = 0; ni < 4; ni++) {
        int c = bn + wn + ni * 8 + s * 2;
        bv[ni].x = bias[c];
        bv[ni].y = bias[c + 1];
    }

    #pragma unroll
    for (int mi = 0; mi < 4; mi++) {
        int r0 = bm + wm + mi * 16 + q;
        int r1 = r0 + 8;
        float di0 = (r0 < N_NODES) ? g_dinv[r0] : 0.0f;
        float di1 = (r1 < N_NODES) ? g_dinv[r1] : 0.0f;
        #pragma unroll
        for (int ni = 0; ni < 4; ni++) {
            int c = bn + wn + ni * 8 + s * 2;
            if (r0 < N_NODES) {
                float o0 = d[mi][ni][0] + bv[ni].x;
                float o1 = d[mi][ni][1] + bv[ni].y;
                *reinterpret_cast<float2*>(&out[(long)r0 * OUT_CH + c]) = make_float2(o0, o1);
                *reinterpret_cast<__half2*>(&mir[(long)r0 * OUT_CH + c]) =
                    __floats2half2_rn(o0 * di0, o1 * di0);
            }
            if (r1 < N_NODES) {
                float o0 = d[mi][ni][2] + bv[ni].x;
                float o1 = d[mi][ni][3] + bv[ni].y;
                *reinterpret_cast<float2*>(&out[(long)r1 * OUT_CH + c]) = make_float2(o0, o1);
                *reinterpret_cast<__half2*>(&mir[(long)r1 * OUT_CH + c]) =
                    __floats2half2_rn(o0 * di1, o1 * di1);
            }
        }
    }
    #undef PREFETCH
    #undef STS
}

// ---------------- SpMM gather: one row per 64-thread block ----------------
// acc = sum over CSR edges of row of h16[col] (mirror already scaled by dinv[col])
// r   = dinv[row] * acc
// out = base ? base + w[widx]*r : r          (fp32, optional)
// mir = fp16(out * dinv[row])                (optional)
__global__ __launch_bounds__(64) void k_spmm(const uint2* __restrict__ h16,
                                             const float4* __restrict__ base4,
                                             const float* __restrict__ wptr,
                                             int widx,
                                             float4* __restrict__ out4,
                                             uint2* __restrict__ mir) {
    __shared__ int scol[256];

    const int row = blockIdx.x;
    const int tid = threadIdx.x;        // 0..63, owns 4 channels
    const int s   = g_rowptr[row];
    const int e   = g_rowptr[row + 1];

    float4 acc = make_float4(0.f, 0.f, 0.f, 0.f);

    for (int bs = s; bs < e; bs += 256) {
        int cnt = min(256, e - bs);
        for (int j = tid; j < cnt; j += 64) scol[j] = g_col[bs + j];
        __syncthreads();
        int j = 0;
        for (; j + 4 <= cnt; j += 4) {
            int c0 = scol[j + 0], c1 = scol[j + 1], c2 = scol[j + 2], c3 = scol[j + 3];
            uint2 u0 = h16[(long)c0 * 64 + tid];
            uint2 u1 = h16[(long)c1 * 64 + tid];
            uint2 u2 = h16[(long)c2 * 64 + tid];
            uint2 u3 = h16[(long)c3 * 64 + tid];
            float2 a0 = __half22float2(*reinterpret_cast<const __half2*>(&u0.x));
            float2 b0 = __half22float2(*reinterpret_cast<const __half2*>(&u0.y));
            float2 a1 = __half22float2(*reinterpret_cast<const __half2*>(&u1.x));
            float2 b1 = __half22float2(*reinterpret_cast<const __half2*>(&u1.y));
            float2 a2 = __half22float2(*reinterpret_cast<const __half2*>(&u2.x));
            float2 b2 = __half22float2(*reinterpret_cast<const __half2*>(&u2.y));
            float2 a3 = __half22float2(*reinterpret_cast<const __half2*>(&u3.x));
            float2 b3 = __half22float2(*reinterpret_cast<const __half2*>(&u3.y));
            acc.x += a0.x + a1.x + a2.x + a3.x;
            acc.y += a0.y + a1.y + a2.y + a3.y;
            acc.z += b0.x + b1.x + b2.x + b3.x;
            acc.w += b0.y + b1.y + b2.y + b3.y;
        }
        for (; j < cnt; j++) {
            uint2 u = h16[(long)scol[j] * 64 + tid];
            float2 a = __half22float2(*reinterpret_cast<const __half2*>(&u.x));
            float2 b = __half22float2(*reinterpret_cast<const __half2*>(&u.y));
            acc.x += a.x; acc.y += a.y; acc.z += b.x; acc.w += b.y;
        }
        __syncthreads();
    }

    const float di = g_dinv[row];
    float4 r;
    r.x = di * acc.x; r.y = di * acc.y; r.z = di * acc.z; r.w = di * acc.w;

    float4 o;
    if (base4 != nullptr) {
        float wk = wptr[widx];
        float4 bv = base4[(long)row * 64 + tid];
        o.x = bv.x + wk * r.x;
        o.y = bv.y + wk * r.y;
        o.z = bv.z + wk * r.z;
        o.w = bv.w + wk * r.w;
    } else {
        o = r;
    }
    if (out4 != nullptr) out4[(long)row * 64 + tid] = o;
    if (mir != nullptr) {
        __half h[4];
        h[0] = __float2half(o.x * di);
        h[1] = __float2half(o.y * di);
        h[2] = __float2half(o.z * di);
        h[3] = __float2half(o.w * di);
        mir[(long)row * 64 + tid] = *reinterpret_cast<const uint2*>(h);
    }
}

// ---------------- launch ----------------
extern "C" void kernel_launch(void* const* d_in, const int* in_sizes, int n_in,
                              void* d_out, int out_size) {
    const float* x   = (const float*)d_in[0];
    const int*   ei  = (const int*)d_in[1];      // edge_index delivered as int32
    const float* lw  = (const float*)d_in[2];
    const float* lb  = (const float*)d_in[3];
    const float* wts = (const float*)d_in[4];
    float*       out = (float*)d_out;

    float* bufB;  __half *m0, *m1, *m2;
    __nv_bfloat16 *xh, *xl, *wh, *wl;
    cudaGetSymbolAddress((void**)&bufB, g_bufB);
    cudaGetSymbolAddress((void**)&m0, g_m0);
    cudaGetSymbolAddress((void**)&m1, g_m1);
    cudaGetSymbolAddress((void**)&m2, g_m2);
    cudaGetSymbolAddress((void**)&xh, g_xh);
    cudaGetSymbolAddress((void**)&xl, g_xl);
    cudaGetSymbolAddress((void**)&wh, g_wh);
    cudaGetSymbolAddress((void**)&wl, g_wl);

    // CSR build (scan computes dinv before GEMM epilogue needs it)
    k_zero_deg<<<(N_NODES + 255) / 256, 256>>>();
    k_count<<<(E_EDGES + 255) / 256, 256>>>(ei);
    k_scan<<<1, 1024>>>();

    // bf16 hi/lo splits of x and W
    {
        int n4 = (N_NODES * IN_CH) / 4;
        k_cvt<<<(n4 + 255) / 256, 256>>>((const float4*)x, (uint2*)xh, (uint2*)xl, n4);
        int w4 = (OUT_CH * IN_CH) / 4;
        k_cvt<<<(w4 + 255) / 256, 256>>>((const float4*)lw, (uint2*)wh, (uint2*)wl, w4);
    }

    // out0 = x @ W^T + b -> d_out ; m0 = fp16(out0 * dinv)
    dim3 ggrid((N_NODES + GBM - 1) / GBM, OUT_CH / GBN);
    k_gemm_mma<<<ggrid, 128>>>(lb, out, m0);

    k_fill<<<(E_EDGES + 255) / 256, 256>>>(ei);

    // k=0: bufB = out0 + w0 * A(out0); m1 = fp16(bufB * dinv)
    k_spmm<<<N_NODES, 64>>>((const uint2*)m0, (const float4*)out, wts, 0,
                            (float4*)bufB, (uint2*)m1);
    // k=1 hop 1: m2 = fp16(A(bufB) * dinv)   (fp32 output not needed)
    k_spmm<<<N_NODES, 64>>>((const uint2*)m1, nullptr, wts, 0,
                            nullptr, (uint2*)m2);
    // k=1 hop 2: d_out = bufB + w1 * A(prev)
    k_spmm<<<N_NODES, 64>>>((const uint2*)m2, (const float4*)bufB, wts, 1,
                            (float4*)out, nullptr);
}

// round 7
// speedup vs baseline: 1.8155x; 1.2564x over previous
#include <cuda_runtime.h>
#include <cuda_fp16.h>
#include <cuda_bf16.h>
#include <cstdint>

#define N_NODES 10000
#define E_EDGES 640000
#define IN_CH   512
#define OUT_CH  256

// ---------------- device-global scratch (no allocations allowed) ----------------
__device__ int    g_deg[N_NODES];
__device__ int    g_rowptr[N_NODES + 1];
__device__ int    g_cursor[N_NODES];
__device__ float  g_dinv[N_NODES];
__device__ int    g_col[E_EDGES];
__device__ float  g_bufB[N_NODES * OUT_CH];
// fp16 gather mirrors (pre-scaled by dinv[row])
__device__ __half g_m0[N_NODES * OUT_CH];
__device__ __half g_m1[N_NODES * OUT_CH];
__device__ __half g_m2[N_NODES * OUT_CH];
// bf16 hi/lo split of the weight matrix
__device__ __nv_bfloat16 g_wh[OUT_CH * IN_CH];
__device__ __nv_bfloat16 g_wl[OUT_CH * IN_CH];

// ---------------- CSR construction ----------------
// edge_index delivered as int32: ei[0..E) = row, ei[E..2E) = col
__global__ void k_count(const int4* __restrict__ ei4) {
    int i = blockIdx.x * blockDim.x + threadIdx.x;
    if (i < E_EDGES / 4) {
        int4 r = ei4[i];
        atomicAdd(&g_deg[min(max(r.x, 0), N_NODES - 1)], 1);
        atomicAdd(&g_deg[min(max(r.y, 0), N_NODES - 1)], 1);
        atomicAdd(&g_deg[min(max(r.z, 0), N_NODES - 1)], 1);
        atomicAdd(&g_deg[min(max(r.w, 0), N_NODES - 1)], 1);
    }
}

// 1-block register-blocked scan: 1024 threads x 10 elements each (10240 >= N)
#define SCAN_PER 10
__global__ __launch_bounds__(1024) void k_scan() {
    const int tid  = threadIdx.x;
    const int lane = tid & 31;
    const int wid  = tid >> 5;
    const int base = tid * SCAN_PER;

    int excl_local[SCAN_PER];
    int sum = 0;
    #pragma unroll
    for (int q = 0; q < SCAN_PER; q++) {
        int i = base + q;
        int v = (i < N_NODES) ? g_deg[i] : 0;
        excl_local[q] = sum;
        sum += v;
    }

    int inc = sum;
    #pragma unroll
    for (int off = 1; off < 32; off <<= 1) {
        int t = __shfl_up_sync(0xFFFFFFFFu, inc, off);
        if (lane >= off) inc += t;
    }

    __shared__ int wsum[32];
    if (lane == 31) wsum[wid] = inc;
    __syncthreads();
    if (wid == 0) {
        int v = wsum[lane];
        int wi = v;
        #pragma unroll
        for (int off = 1; off < 32; off <<= 1) {
            int t = __shfl_up_sync(0xFFFFFFFFu, wi, off);
            if (lane >= off) wi += t;
        }
        wsum[lane] = wi - v;
    }
    __syncthreads();

    const int offset = wsum[wid] + (inc - sum);

    #pragma unroll
    for (int q = 0; q < SCAN_PER; q++) {
        int i = base + q;
        if (i < N_NODES) {
            int excl = offset + excl_local[q];
            g_rowptr[i] = excl;
            g_cursor[i] = excl;
            int d = g_deg[i];
            g_dinv[i] = (d > 0) ? rsqrtf((float)d) : 0.0f;
        }
    }
    if (tid == 1023) g_rowptr[N_NODES] = offset + sum;
}

__global__ void k_fill(const int4* __restrict__ ei4) {
    int i = blockIdx.x * blockDim.x + threadIdx.x;
    if (i < E_EDGES / 4) {
        int4 r = ei4[i];
        int4 c = ei4[E_EDGES / 4 + i];
        int rr[4] = {r.x, r.y, r.z, r.w};
        int cc[4] = {c.x, c.y, c.z, c.w};
        #pragma unroll
        for (int q = 0; q < 4; q++) {
            int rv = min(max(rr[q], 0), N_NODES - 1);
            int cv = min(max(cc[q], 0), N_NODES - 1);
            int pos = atomicAdd(&g_cursor[rv], 1);
            if (pos >= 0 && pos < E_EDGES) g_col[pos] = cv;
        }
    }
}

// ---------------- bf16 hi/lo split conversion (weights only) ----------------
__global__ void k_cvt(const float4* __restrict__ src,
                      uint2* __restrict__ hi, uint2* __restrict__ lo, int n4) {
    int i = blockIdx.x * blockDim.x + threadIdx.x;
    if (i < n4) {
        float4 v = src[i];
        __nv_bfloat16 h[4], l[4];
        h[0] = __float2bfloat16_rn(v.x); l[0] = __float2bfloat16_rn(v.x - __bfloat162float(h[0]));
        h[1] = __float2bfloat16_rn(v.y); l[1] = __float2bfloat16_rn(v.y - __bfloat162float(h[1]));
        h[2] = __float2bfloat16_rn(v.z); l[2] = __float2bfloat16_rn(v.z - __bfloat162float(h[2]));
        h[3] = __float2bfloat16_rn(v.w); l[3] = __float2bfloat16_rn(v.w - __bfloat162float(h[3]));
        hi[i] = *reinterpret_cast<const uint2*>(h);
        lo[i] = *reinterpret_cast<const uint2*>(l);
    }
}

// ---------------- Tensor-core GEMM (bf16x3 via mma.sync, fp32 accum) ----------------
// out[n,o] = sum_k x[n,k]*W[o,k] + b[o]; also mir = fp16(out*dinv[n]).
// CTA tile 64x64, 4 warps, warp tile 32x32, mma.m16n8k16, k16 chunks.
// x is converted fp32 -> bf16 hi/lo in-kernel; 3 segment MMAs per chunk:
//   Ah*Wh + Al*Wh + Ah*Wl  (all into the same fp32 accumulators).
#define GBM 64
#define GBN 64
#define SMSTRIDE 24   // bf16 elements per smem row (16 data + 8 pad) -> conflict-free

__global__ __launch_bounds__(128) void k_gemm_mma(const float* __restrict__ x,
                                                  const float* __restrict__ bias,
                                                  float* __restrict__ out,
                                                  __half* __restrict__ mir) {
    __shared__ __nv_bfloat16 Ah[2][GBM][SMSTRIDE];
    __shared__ __nv_bfloat16 Al[2][GBM][SMSTRIDE];
    __shared__ __nv_bfloat16 Wh[2][GBN][SMSTRIDE];
    __shared__ __nv_bfloat16 Wl[2][GBN][SMSTRIDE];

    const int tid  = threadIdx.x;
    const int wid  = tid >> 5;
    const int lane = tid & 31;
    const int bm   = blockIdx.x * GBM;
    const int bn   = blockIdx.y * GBN;
    const int wm   = (wid & 1) * 32;
    const int wn   = (wid >> 1) * 32;
    const int q    = lane >> 2;         // 0..7
    const int s    = lane & 3;          // 0..3

    // loader geometry: each thread owns (row = tid/2, k-offset = (tid&1)*8), 8 elements
    const int lr = tid >> 1;
    const int lk = (tid & 1) * 8;

    float d[2][4][4];
    #pragma unroll
    for (int mi = 0; mi < 2; mi++)
        #pragma unroll
        for (int ni = 0; ni < 4; ni++)
            #pragma unroll
            for (int r = 0; r < 4; r++) d[mi][ni][r] = 0.0f;

    float4 px0, px1;
    uint4  pwh, pwl;
    const float4 zf4 = make_float4(0.f, 0.f, 0.f, 0.f);

    #define PF(ch)                                                               \
    {                                                                            \
        int k0_ = (ch) * 16;                                                     \
        int m_  = bm + lr;                                                       \
        if (m_ < N_NODES) {                                                      \
            const float4* p_ = reinterpret_cast<const float4*>(&x[(long)m_ * IN_CH + k0_ + lk]); \
            px0 = p_[0]; px1 = p_[1];                                            \
        } else { px0 = zf4; px1 = zf4; }                                         \
        pwh = *reinterpret_cast<const uint4*>(&g_wh[(long)(bn + lr) * IN_CH + k0_ + lk]); \
        pwl = *reinterpret_cast<const uint4*>(&g_wl[(long)(bn + lr) * IN_CH + k0_ + lk]); \
    }

    #define STS(buf)                                                             \
    {                                                                            \
        float f_[8] = {px0.x, px0.y, px0.z, px0.w, px1.x, px1.y, px1.z, px1.w};  \
        __nv_bfloat16 h_[8], l_[8];                                              \
        _Pragma("unroll")                                                        \
        for (int u = 0; u < 8; u++) {                                            \
            h_[u] = __float2bfloat16_rn(f_[u]);                                  \
            l_[u] = __float2bfloat16_rn(f_[u] - __bfloat162float(h_[u]));        \
        }                                                                        \
        *reinterpret_cast<uint4*>(&Ah[buf][lr][lk]) = *reinterpret_cast<const uint4*>(h_); \
        *reinterpret_cast<uint4*>(&Al[buf][lr][lk]) = *reinterpret_cast<const uint4*>(l_); \
        *reinterpret_cast<uint4*>(&Wh[buf][lr][lk]) = pwh;                       \
        *reinterpret_cast<uint4*>(&Wl[buf][lr][lk]) = pwl;                       \
    }

    int buf = 0;
    PF(0);
    STS(0);
    __syncthreads();

    const int NCHUNK = IN_CH / 16;   // 32
    for (int ch = 0; ch < NCHUNK; ch++) {
        if (ch + 1 < NCHUNK) PF(ch + 1);

        // B fragments (hi and lo) for this warp's 4 n-tiles
        unsigned bh[4][2], bl[4][2];
        #pragma unroll
        for (int ni = 0; ni < 4; ni++) {
            const __nv_bfloat16* ph = &Wh[buf][wn + ni * 8 + q][s * 2];
            bh[ni][0] = *reinterpret_cast<const unsigned*>(ph);
            bh[ni][1] = *reinterpret_cast<const unsigned*>(ph + 8);
            const __nv_bfloat16* pl = &Wl[buf][wn + ni * 8 + q][s * 2];
            bl[ni][0] = *reinterpret_cast<const unsigned*>(pl);
            bl[ni][1] = *reinterpret_cast<const unsigned*>(pl + 8);
        }
        #pragma unroll
        for (int mi = 0; mi < 2; mi++) {
            const __nv_bfloat16* pah = &Ah[buf][wm + mi * 16 + q][s * 2];
            unsigned ah0 = *reinterpret_cast<const unsigned*>(pah);
            unsigned ah1 = *reinterpret_cast<const unsigned*>(pah + 8 * SMSTRIDE);
            unsigned ah2 = *reinterpret_cast<const unsigned*>(pah + 8);
            unsigned ah3 = *reinterpret_cast<const unsigned*>(pah + 8 * SMSTRIDE + 8);
            const __nv_bfloat16* pal = &Al[buf][wm + mi * 16 + q][s * 2];
            unsigned al0 = *reinterpret_cast<const unsigned*>(pal);
            unsigned al1 = *reinterpret_cast<const unsigned*>(pal + 8 * SMSTRIDE);
            unsigned al2 = *reinterpret_cast<const unsigned*>(pal + 8);
            unsigned al3 = *reinterpret_cast<const unsigned*>(pal + 8 * SMSTRIDE + 8);
            #pragma unroll
            for (int ni = 0; ni < 4; ni++) {
                asm volatile(
                    "mma.sync.aligned.m16n8k16.row.col.f32.bf16.bf16.f32 "
                    "{%0,%1,%2,%3}, {%4,%5,%6,%7}, {%8,%9}, {%0,%1,%2,%3};"
                    : "+f"(d[mi][ni][0]), "+f"(d[mi][ni][1]),
                      "+f"(d[mi][ni][2]), "+f"(d[mi][ni][3])
                    : "r"(ah0), "r"(ah1), "r"(ah2), "r"(ah3),
                      "r"(bh[ni][0]), "r"(bh[ni][1]));
                asm volatile(
                    "mma.sync.aligned.m16n8k16.row.col.f32.bf16.bf16.f32 "
                    "{%0,%1,%2,%3}, {%4,%5,%6,%7}, {%8,%9}, {%0,%1,%2,%3};"
                    : "+f"(d[mi][ni][0]), "+f"(d[mi][ni][1]),
                      "+f"(d[mi][ni][2]), "+f"(d[mi][ni][3])
                    : "r"(al0), "r"(al1), "r"(al2), "r"(al3),
                      "r"(bh[ni][0]), "r"(bh[ni][1]));
                asm volatile(
                    "mma.sync.aligned.m16n8k16.row.col.f32.bf16.bf16.f32 "
                    "{%0,%1,%2,%3}, {%4,%5,%6,%7}, {%8,%9}, {%0,%1,%2,%3};"
                    : "+f"(d[mi][ni][0]), "+f"(d[mi][ni][1]),
                      "+f"(d[mi][ni][2]), "+f"(d[mi][ni][3])
                    : "r"(ah0), "r"(ah1), "r"(ah2), "r"(ah3),
                      "r"(bl[ni][0]), "r"(bl[ni][1]));
            }
        }

        if (ch + 1 < NCHUNK) {
            STS(buf ^ 1);
            __syncthreads();
            buf ^= 1;
        }
    }
    #undef PF
    #undef STS

    // ---- epilogue: bias, fp32 out, fp16 mirror (scaled by dinv) ----
    float2 bv[4];
    #pragma unroll
    for (int ni = 0; ni < 4; ni++) {
        int c = bn + wn + ni * 8 + s * 2;
        bv[ni].x = bias[c];
        bv[ni].y = bias[c + 1];
    }

    #pragma unroll
    for (int mi = 0; mi < 2; mi++) {
        int r0 = bm + wm + mi * 16 + q;
        int r1 = r0 + 8;
        float di0 = (r0 < N_NODES) ? g_dinv[r0] : 0.0f;
        float di1 = (r1 < N_NODES) ? g_dinv[r1] : 0.0f;
        #pragma unroll
        for (int ni = 0; ni < 4; ni++) {
            int c = bn + wn + ni * 8 + s * 2;
            if (r0 < N_NODES) {
                float o0 = d[mi][ni][0] + bv[ni].x;
                float o1 = d[mi][ni][1] + bv[ni].y;
                *reinterpret_cast<float2*>(&out[(long)r0 * OUT_CH + c]) = make_float2(o0, o1);
                *reinterpret_cast<__half2*>(&mir[(long)r0 * OUT_CH + c]) =
                    __floats2half2_rn(o0 * di0, o1 * di0);
            }
            if (r1 < N_NODES) {
                float o0 = d[mi][ni][2] + bv[ni].x;
                float o1 = d[mi][ni][3] + bv[ni].y;
                *reinterpret_cast<float2*>(&out[(long)r1 * OUT_CH + c]) = make_float2(o0, o1);
                *reinterpret_cast<__half2*>(&mir[(long)r1 * OUT_CH + c]) =
                    __floats2half2_rn(o0 * di1, o1 * di1);
            }
        }
    }
}

// ---------------- SpMM gather: one row per 64-thread block ----------------
__global__ __launch_bounds__(64) void k_spmm(const uint2* __restrict__ h16,
                                             const float4* __restrict__ base4,
                                             const float* __restrict__ wptr,
                                             int widx,
                                             float4* __restrict__ out4,
                                             uint2* __restrict__ mir) {
    __shared__ int scol[256];

    const int row = blockIdx.x;
    const int tid = threadIdx.x;        // 0..63, owns 4 channels
    const int s   = g_rowptr[row];
    const int e   = g_rowptr[row + 1];

    float4 acc = make_float4(0.f, 0.f, 0.f, 0.f);

    for (int bs = s; bs < e; bs += 256) {
        int cnt = min(256, e - bs);
        for (int j = tid; j < cnt; j += 64) scol[j] = g_col[bs + j];
        __syncthreads();
        int j = 0;
        for (; j + 4 <= cnt; j += 4) {
            int c0 = scol[j + 0], c1 = scol[j + 1], c2 = scol[j + 2], c3 = scol[j + 3];
            uint2 u0 = h16[(long)c0 * 64 + tid];
            uint2 u1 = h16[(long)c1 * 64 + tid];
            uint2 u2 = h16[(long)c2 * 64 + tid];
            uint2 u3 = h16[(long)c3 * 64 + tid];
            float2 a0 = __half22float2(*reinterpret_cast<const __half2*>(&u0.x));
            float2 b0 = __half22float2(*reinterpret_cast<const __half2*>(&u0.y));
            float2 a1 = __half22float2(*reinterpret_cast<const __half2*>(&u1.x));
            float2 b1 = __half22float2(*reinterpret_cast<const __half2*>(&u1.y));
            float2 a2 = __half22float2(*reinterpret_cast<const __half2*>(&u2.x));
            float2 b2 = __half22float2(*reinterpret_cast<const __half2*>(&u2.y));
            float2 a3 = __half22float2(*reinterpret_cast<const __half2*>(&u3.x));
            float2 b3 = __half22float2(*reinterpret_cast<const __half2*>(&u3.y));
            acc.x += a0.x + a1.x + a2.x + a3.x;
            acc.y += a0.y + a1.y + a2.y + a3.y;
            acc.z += b0.x + b1.x + b2.x + b3.x;
            acc.w += b0.y + b1.y + b2.y + b3.y;
        }
        for (; j < cnt; j++) {
            uint2 u = h16[(long)scol[j] * 64 + tid];
            float2 a = __half22float2(*reinterpret_cast<const __half2*>(&u.x));
            float2 b = __half22float2(*reinterpret_cast<const __half2*>(&u.y));
            acc.x += a.x; acc.y += a.y; acc.z += b.x; acc.w += b.y;
        }
        __syncthreads();
    }

    const float di = g_dinv[row];
    float4 r;
    r.x = di * acc.x; r.y = di * acc.y; r.z = di * acc.z; r.w = di * acc.w;

    float4 o;
    if (base4 != nullptr) {
        float wk = wptr[widx];
        float4 bv = base4[(long)row * 64 + tid];
        o.x = bv.x + wk * r.x;
        o.y = bv.y + wk * r.y;
        o.z = bv.z + wk * r.z;
        o.w = bv.w + wk * r.w;
    } else {
        o = r;
    }
    if (out4 != nullptr) out4[(long)row * 64 + tid] = o;
    if (mir != nullptr) {
        __half h[4];
        h[0] = __float2half(o.x * di);
        h[1] = __float2half(o.y * di);
        h[2] = __float2half(o.z * di);
        h[3] = __float2half(o.w * di);
        mir[(long)row * 64 + tid] = *reinterpret_cast<const uint2*>(h);
    }
}

// ---------------- launch ----------------
extern "C" void kernel_launch(void* const* d_in, const int* in_sizes, int n_in,
                              void* d_out, int out_size) {
    const float* x   = (const float*)d_in[0];
    const int*   ei  = (const int*)d_in[1];      // edge_index delivered as int32
    const float* lw  = (const float*)d_in[2];
    const float* lb  = (const float*)d_in[3];
    const float* wts = (const float*)d_in[4];
    float*       out = (float*)d_out;

    float* bufB;  __half *m0, *m1, *m2;
    __nv_bfloat16 *wh, *wl;
    int* degp;
    cudaGetSymbolAddress((void**)&bufB, g_bufB);
    cudaGetSymbolAddress((void**)&m0, g_m0);
    cudaGetSymbolAddress((void**)&m1, g_m1);
    cudaGetSymbolAddress((void**)&m2, g_m2);
    cudaGetSymbolAddress((void**)&wh, g_wh);
    cudaGetSymbolAddress((void**)&wl, g_wl);
    cudaGetSymbolAddress((void**)&degp, g_deg);

    // CSR degree + scan (dinv needed by GEMM epilogue)
    cudaMemsetAsync(degp, 0, N_NODES * sizeof(int));
    k_count<<<(E_EDGES / 4 + 255) / 256, 256>>>((const int4*)ei);
    k_scan<<<1, 1024>>>();

    // bf16 hi/lo split of W (x is split in-kernel)
    {
        int w4 = (OUT_CH * IN_CH) / 4;
        k_cvt<<<(w4 + 255) / 256, 256>>>((const float4*)lw, (uint2*)wh, (uint2*)wl, w4);
    }

    // out0 = x @ W^T + b -> d_out ; m0 = fp16(out0 * dinv)
    dim3 ggrid((N_NODES + GBM - 1) / GBM, OUT_CH / GBN);
    k_gemm_mma<<<ggrid, 128>>>(x, lb, out, m0);

    k_fill<<<(E_EDGES / 4 + 255) / 256, 256>>>((const int4*)ei);

    // k=0: bufB = out0 + w0 * A(out0); m1 = fp16(bufB * dinv)
    k_spmm<<<N_NODES, 64>>>((const uint2*)m0, (const float4*)out, wts, 0,
                            (float4*)bufB, (uint2*)m1);
    // k=1 hop 1: m2 = fp16(A(bufB) * dinv)   (fp32 output not needed)
    k_spmm<<<N_NODES, 64>>>((const uint2*)m1, nullptr, wts, 0,
                            nullptr, (uint2*)m2);
    // k=1 hop 2: d_out = bufB + w1 * A(prev)
    k_spmm<<<N_NODES, 64>>>((const uint2*)m2, (const float4*)bufB, wts, 1,
                            (float4*)out, nullptr);
}

// round 8
// speedup vs baseline: 1.8815x; 1.0363x over previous
#include <cuda_runtime.h>
#include <cuda_fp16.h>
#include <cuda_bf16.h>
#include <cstdint>

#define N_NODES 10000
#define E_EDGES 640000
#define IN_CH   512
#define OUT_CH  256

// ---------------- device-global scratch (no allocations allowed) ----------------
__device__ int    g_deg[N_NODES];
__device__ int    g_rowptr[N_NODES + 1];
__device__ int    g_cursor[N_NODES];
__device__ float  g_dinv[N_NODES];
__device__ int    g_col[E_EDGES];
__device__ float  g_bufB[N_NODES * OUT_CH];
// fp16 gather mirrors (pre-scaled by dinv[row])
__device__ __half g_m0[N_NODES * OUT_CH];
__device__ __half g_m1[N_NODES * OUT_CH];
__device__ __half g_m2[N_NODES * OUT_CH];
// bf16 hi/lo split of the weight matrix
__device__ __nv_bfloat16 g_wh[OUT_CH * IN_CH];
__device__ __nv_bfloat16 g_wl[OUT_CH * IN_CH];

__device__ __forceinline__ uint32_t smem_u32(const void* p) {
    uint32_t a;
    asm("{ .reg .u64 t; cvta.to.shared.u64 t, %1; cvt.u32.u64 %0, t; }" : "=r"(a) : "l"(p));
    return a;
}

#define LDSM_X4(r0, r1, r2, r3, addr) \
    asm volatile("ldmatrix.sync.aligned.m8n8.x4.shared.b16 {%0,%1,%2,%3}, [%4];" \
                 : "=r"(r0), "=r"(r1), "=r"(r2), "=r"(r3) : "r"(addr))

#define MMA_BF16(d, a, b0, b1) \
    asm volatile( \
        "mma.sync.aligned.m16n8k16.row.col.f32.bf16.bf16.f32 " \
        "{%0,%1,%2,%3}, {%4,%5,%6,%7}, {%8,%9}, {%0,%1,%2,%3};" \
        : "+f"((d)[0]), "+f"((d)[1]), "+f"((d)[2]), "+f"((d)[3]) \
        : "r"((a)[0]), "r"((a)[1]), "r"((a)[2]), "r"((a)[3]), "r"(b0), "r"(b1))

// ---------------- CSR construction ----------------
// edge_index delivered as int32: ei[0..E) = row, ei[E..2E) = col
__global__ void k_count(const int4* __restrict__ ei4) {
    int i = blockIdx.x * blockDim.x + threadIdx.x;
    if (i < E_EDGES / 4) {
        int4 r = ei4[i];
        atomicAdd(&g_deg[min(max(r.x, 0), N_NODES - 1)], 1);
        atomicAdd(&g_deg[min(max(r.y, 0), N_NODES - 1)], 1);
        atomicAdd(&g_deg[min(max(r.z, 0), N_NODES - 1)], 1);
        atomicAdd(&g_deg[min(max(r.w, 0), N_NODES - 1)], 1);
    }
}

// 1-block register-blocked scan: 1024 threads x 10 elements each (10240 >= N)
#define SCAN_PER 10
__global__ __launch_bounds__(1024) void k_scan() {
    const int tid  = threadIdx.x;
    const int lane = tid & 31;
    const int wid  = tid >> 5;
    const int base = tid * SCAN_PER;

    int excl_local[SCAN_PER];
    int sum = 0;
    #pragma unroll
    for (int q = 0; q < SCAN_PER; q++) {
        int i = base + q;
        int v = (i < N_NODES) ? g_deg[i] : 0;
        excl_local[q] = sum;
        sum += v;
    }

    int inc = sum;
    #pragma unroll
    for (int off = 1; off < 32; off <<= 1) {
        int t = __shfl_up_sync(0xFFFFFFFFu, inc, off);
        if (lane >= off) inc += t;
    }

    __shared__ int wsum[32];
    if (lane == 31) wsum[wid] = inc;
    __syncthreads();
    if (wid == 0) {
        int v = wsum[lane];
        int wi = v;
        #pragma unroll
        for (int off = 1; off < 32; off <<= 1) {
            int t = __shfl_up_sync(0xFFFFFFFFu, wi, off);
            if (lane >= off) wi += t;
        }
        wsum[lane] = wi - v;
    }
    __syncthreads();

    const int offset = wsum[wid] + (inc - sum);

    #pragma unroll
    for (int q = 0; q < SCAN_PER; q++) {
        int i = base + q;
        if (i < N_NODES) {
            int excl = offset + excl_local[q];
            g_rowptr[i] = excl;
            g_cursor[i] = excl;
            int d = g_deg[i];
            g_dinv[i] = (d > 0) ? rsqrtf((float)d) : 0.0f;
        }
    }
    if (tid == 1023) g_rowptr[N_NODES] = offset + sum;
}

__global__ void k_fill(const int4* __restrict__ ei4) {
    int i = blockIdx.x * blockDim.x + threadIdx.x;
    if (i < E_EDGES / 4) {
        int4 r = ei4[i];
        int4 c = ei4[E_EDGES / 4 + i];
        int rr[4] = {r.x, r.y, r.z, r.w};
        int cc[4] = {c.x, c.y, c.z, c.w};
        #pragma unroll
        for (int q = 0; q < 4; q++) {
            int rv = min(max(rr[q], 0), N_NODES - 1);
            int cv = min(max(cc[q], 0), N_NODES - 1);
            int pos = atomicAdd(&g_cursor[rv], 1);
            if (pos >= 0 && pos < E_EDGES) g_col[pos] = cv;
        }
    }
}

// ---------------- bf16 hi/lo split conversion (weights only) ----------------
__global__ void k_cvt(const float4* __restrict__ src,
                      uint2* __restrict__ hi, uint2* __restrict__ lo, int n4) {
    int i = blockIdx.x * blockDim.x + threadIdx.x;
    if (i < n4) {
        float4 v = src[i];
        __nv_bfloat16 h[4], l[4];
        h[0] = __float2bfloat16_rn(v.x); l[0] = __float2bfloat16_rn(v.x - __bfloat162float(h[0]));
        h[1] = __float2bfloat16_rn(v.y); l[1] = __float2bfloat16_rn(v.y - __bfloat162float(h[1]));
        h[2] = __float2bfloat16_rn(v.z); l[2] = __float2bfloat16_rn(v.z - __bfloat162float(h[2]));
        h[3] = __float2bfloat16_rn(v.w); l[3] = __float2bfloat16_rn(v.w - __bfloat162float(h[3]));
        hi[i] = *reinterpret_cast<const uint2*>(h);
        lo[i] = *reinterpret_cast<const uint2*>(l);
    }
}

// ---------------- Tensor-core GEMM (bf16x3 via mma.sync + ldmatrix) ----------------
// out[n,o] = sum_k x[n,k]*W[o,k] + b[o]; also mir = fp16(out*dinv[n]).
// CTA tile 64x64, 4 warps, warp tile 32x32, mma.m16n8k16, k16 chunks.
// x is converted fp32 -> bf16 hi/lo in-kernel; 3 segment passes per chunk:
//   Ah*Wh + Al*Wh + Ah*Wl  (all into the same fp32 accumulators).
#define GBM 64
#define GBN 64
#define SMSTRIDE 24   // bf16 elements per smem row (16 data + 8 pad); 48B stride -> LDSM conflict-free

__global__ __launch_bounds__(128) void k_gemm_mma(const float* __restrict__ x,
                                                  const float* __restrict__ bias,
                                                  float* __restrict__ out,
                                                  __half* __restrict__ mir) {
    __shared__ __nv_bfloat16 Ah[2][GBM][SMSTRIDE];
    __shared__ __nv_bfloat16 Al[2][GBM][SMSTRIDE];
    __shared__ __nv_bfloat16 Wh[2][GBN][SMSTRIDE];
    __shared__ __nv_bfloat16 Wl[2][GBN][SMSTRIDE];

    const int tid  = threadIdx.x;
    const int wid  = tid >> 5;
    const int lane = tid & 31;
    const int bm   = blockIdx.x * GBM;
    const int bn   = blockIdx.y * GBN;
    const int wm   = (wid & 1) * 32;
    const int wn   = (wid >> 1) * 32;
    const int q    = lane >> 2;         // 0..7
    const int s    = lane & 3;          // 0..3

    // ldmatrix lane geometry
    const int lg   = lane >> 3;         // 0..3
    const int l8   = lane & 7;
    const int arow = l8 + ((lg & 1) << 3);   // A: rows (m), groups 0/1 = rows 0-7/8-15
    const int acol = (lg >> 1) << 3;         //    groups 2/3 = k cols 8-15
    const int brow = l8 + ((lg >> 1) << 3);  // B: groups 0/1 = first n-tile, 2/3 = second
    const int bcol = (lg & 1) << 3;

    // per-lane LDSM base addresses (byte offsets within the [2][64][24] arrays)
    const int aoffB = ((wm + arow) * SMSTRIDE + acol) * 2;
    const int boffB = ((wn + brow) * SMSTRIDE + bcol) * 2;
    const uint32_t aBaseH = smem_u32(&Ah[0][0][0]) + aoffB;
    const uint32_t aBaseL = smem_u32(&Al[0][0][0]) + aoffB;
    const uint32_t bBaseH = smem_u32(&Wh[0][0][0]) + boffB;
    const uint32_t bBaseL = smem_u32(&Wl[0][0][0]) + boffB;
    const int BUFB = GBM * SMSTRIDE * 2;     // 3072 bytes per buffer
    const int MI_B = 16 * SMSTRIDE * 2;      // 768 bytes per 16-row step

    // loader geometry: each thread owns (row = tid/2, k-offset = (tid&1)*8), 8 elements
    const int lr = tid >> 1;
    const int lk = (tid & 1) * 8;

    float d[2][4][4];
    #pragma unroll
    for (int mi = 0; mi < 2; mi++)
        #pragma unroll
        for (int ni = 0; ni < 4; ni++)
            #pragma unroll
            for (int r = 0; r < 4; r++) d[mi][ni][r] = 0.0f;

    float4 px0, px1;
    uint4  pwh, pwl;
    const float4 zf4 = make_float4(0.f, 0.f, 0.f, 0.f);

    #define PF(ch)                                                               \
    {                                                                            \
        int k0_ = (ch) * 16;                                                     \
        int m_  = bm + lr;                                                       \
        if (m_ < N_NODES) {                                                      \
            const float4* p_ = reinterpret_cast<const float4*>(&x[(long)m_ * IN_CH + k0_ + lk]); \
            px0 = p_[0]; px1 = p_[1];                                            \
        } else { px0 = zf4; px1 = zf4; }                                         \
        pwh = *reinterpret_cast<const uint4*>(&g_wh[(long)(bn + lr) * IN_CH + k0_ + lk]); \
        pwl = *reinterpret_cast<const uint4*>(&g_wl[(long)(bn + lr) * IN_CH + k0_ + lk]); \
    }

    #define STS(buf)                                                             \
    {                                                                            \
        float f_[8] = {px0.x, px0.y, px0.z, px0.w, px1.x, px1.y, px1.z, px1.w};  \
        __nv_bfloat16 h_[8], l_[8];                                              \
        _Pragma("unroll")                                                        \
        for (int u = 0; u < 8; u++) {                                            \
            h_[u] = __float2bfloat16_rn(f_[u]);                                  \
            l_[u] = __float2bfloat16_rn(f_[u] - __bfloat162float(h_[u]));        \
        }                                                                        \
        *reinterpret_cast<uint4*>(&Ah[buf][lr][lk]) = *reinterpret_cast<const uint4*>(h_); \
        *reinterpret_cast<uint4*>(&Al[buf][lr][lk]) = *reinterpret_cast<const uint4*>(l_); \
        *reinterpret_cast<uint4*>(&Wh[buf][lr][lk]) = pwh;                       \
        *reinterpret_cast<uint4*>(&Wl[buf][lr][lk]) = pwl;                       \
    }

    int buf = 0;
    PF(0);
    STS(0);
    __syncthreads();

    const int NCHUNK = IN_CH / 16;   // 32
    for (int ch = 0; ch < NCHUNK; ch++) {
        if (ch + 1 < NCHUNK) PF(ch + 1);

        const int bo = buf * BUFB;

        // fragment loads via ldmatrix (8 LDSM per warp-chunk)
        unsigned ah[2][4], al[2][4], bh[4][2], bl[4][2];
        #pragma unroll
        for (int mi = 0; mi < 2; mi++) {
            LDSM_X4(ah[mi][0], ah[mi][1], ah[mi][2], ah[mi][3], aBaseH + bo + mi * MI_B);
            LDSM_X4(al[mi][0], al[mi][1], al[mi][2], al[mi][3], aBaseL + bo + mi * MI_B);
        }
        #pragma unroll
        for (int p = 0; p < 2; p++) {
            unsigned t0, t1, t2, t3;
            LDSM_X4(t0, t1, t2, t3, bBaseH + bo + p * MI_B);
            bh[2 * p][0] = t0; bh[2 * p][1] = t1;
            bh[2 * p + 1][0] = t2; bh[2 * p + 1][1] = t3;
            LDSM_X4(t0, t1, t2, t3, bBaseL + bo + p * MI_B);
            bl[2 * p][0] = t0; bl[2 * p][1] = t1;
            bl[2 * p + 1][0] = t2; bl[2 * p + 1][1] = t3;
        }

        // 3 segments, ni-inner so same-accumulator MMAs are 4 apart
        #pragma unroll
        for (int mi = 0; mi < 2; mi++) {
            #pragma unroll
            for (int ni = 0; ni < 4; ni++) MMA_BF16(d[mi][ni], ah[mi], bh[ni][0], bh[ni][1]);
            #pragma unroll
            for (int ni = 0; ni < 4; ni++) MMA_BF16(d[mi][ni], al[mi], bh[ni][0], bh[ni][1]);
            #pragma unroll
            for (int ni = 0; ni < 4; ni++) MMA_BF16(d[mi][ni], ah[mi], bl[ni][0], bl[ni][1]);
        }

        if (ch + 1 < NCHUNK) {
            STS(buf ^ 1);
            __syncthreads();
            buf ^= 1;
        }
    }
    #undef PF
    #undef STS

    // ---- epilogue: bias, fp32 out, fp16 mirror (scaled by dinv) ----
    float2 bv[4];
    #pragma unroll
    for (int ni = 0; ni < 4; ni++) {
        int c = bn + wn + ni * 8 + s * 2;
        bv[ni].x = bias[c];
        bv[ni].y = bias[c + 1];
    }

    #pragma unroll
    for (int mi = 0; mi < 2; mi++) {
        int r0 = bm + wm + mi * 16 + q;
        int r1 = r0 + 8;
        float di0 = (r0 < N_NODES) ? g_dinv[r0] : 0.0f;
        float di1 = (r1 < N_NODES) ? g_dinv[r1] : 0.0f;
        #pragma unroll
        for (int ni = 0; ni < 4; ni++) {
            int c = bn + wn + ni * 8 + s * 2;
            if (r0 < N_NODES) {
                float o0 = d[mi][ni][0] + bv[ni].x;
                float o1 = d[mi][ni][1] + bv[ni].y;
                *reinterpret_cast<float2*>(&out[(long)r0 * OUT_CH + c]) = make_float2(o0, o1);
                *reinterpret_cast<__half2*>(&mir[(long)r0 * OUT_CH + c]) =
                    __floats2half2_rn(o0 * di0, o1 * di0);
            }
            if (r1 < N_NODES) {
                float o0 = d[mi][ni][2] + bv[ni].x;
                float o1 = d[mi][ni][3] + bv[ni].y;
                *reinterpret_cast<float2*>(&out[(long)r1 * OUT_CH + c]) = make_float2(o0, o1);
                *reinterpret_cast<__half2*>(&mir[(long)r1 * OUT_CH + c]) =
                    __floats2half2_rn(o0 * di1, o1 * di1);
            }
        }
    }
}

// ---------------- SpMM gather: one row per 64-thread block ----------------
__global__ __launch_bounds__(64) void k_spmm(const uint2* __restrict__ h16,
                                             const float4* __restrict__ base4,
                                             const float* __restrict__ wptr,
                                             int widx,
                                             float4* __restrict__ out4,
                                             uint2* __restrict__ mir) {
    __shared__ int scol[256];

    const int row = blockIdx.x;
    const int tid = threadIdx.x;        // 0..63, owns 4 channels
    const int s   = g_rowptr[row];
    const int e   = g_rowptr[row + 1];

    float4 acc = make_float4(0.f, 0.f, 0.f, 0.f);

    for (int bs = s; bs < e; bs += 256) {
        int cnt = min(256, e - bs);
        for (int j = tid; j < cnt; j += 64) scol[j] = g_col[bs + j];
        __syncthreads();
        int j = 0;
        for (; j + 4 <= cnt; j += 4) {
            int c0 = scol[j + 0], c1 = scol[j + 1], c2 = scol[j + 2], c3 = scol[j + 3];
            uint2 u0 = h16[(long)c0 * 64 + tid];
            uint2 u1 = h16[(long)c1 * 64 + tid];
            uint2 u2 = h16[(long)c2 * 64 + tid];
            uint2 u3 = h16[(long)c3 * 64 + tid];
            float2 a0 = __half22float2(*reinterpret_cast<const __half2*>(&u0.x));
            float2 b0 = __half22float2(*reinterpret_cast<const __half2*>(&u0.y));
            float2 a1 = __half22float2(*reinterpret_cast<const __half2*>(&u1.x));
            float2 b1 = __half22float2(*reinterpret_cast<const __half2*>(&u1.y));
            float2 a2 = __half22float2(*reinterpret_cast<const __half2*>(&u2.x));
            float2 b2 = __half22float2(*reinterpret_cast<const __half2*>(&u2.y));
            float2 a3 = __half22float2(*reinterpret_cast<const __half2*>(&u3.x));
            float2 b3 = __half22float2(*reinterpret_cast<const __half2*>(&u3.y));
            acc.x += a0.x + a1.x + a2.x + a3.x;
            acc.y += a0.y + a1.y + a2.y + a3.y;
            acc.z += b0.x + b1.x + b2.x + b3.x;
            acc.w += b0.y + b1.y + b2.y + b3.y;
        }
        for (; j < cnt; j++) {
            uint2 u = h16[(long)scol[j] * 64 + tid];
            float2 a = __half22float2(*reinterpret_cast<const __half2*>(&u.x));
            float2 b = __half22float2(*reinterpret_cast<const __half2*>(&u.y));
            acc.x += a.x; acc.y += a.y; acc.z += b.x; acc.w += b.y;
        }
        __syncthreads();
    }

    const float di = g_dinv[row];
    float4 r;
    r.x = di * acc.x; r.y = di * acc.y; r.z = di * acc.z; r.w = di * acc.w;

    float4 o;
    if (base4 != nullptr) {
        float wk = wptr[widx];
        float4 bv = base4[(long)row * 64 + tid];
        o.x = bv.x + wk * r.x;
        o.y = bv.y + wk * r.y;
        o.z = bv.z + wk * r.z;
        o.w = bv.w + wk * r.w;
    } else {
        o = r;
    }
    if (out4 != nullptr) out4[(long)row * 64 + tid] = o;
    if (mir != nullptr) {
        __half h[4];
        h[0] = __float2half(o.x * di);
        h[1] = __float2half(o.y * di);
        h[2] = __float2half(o.z * di);
        h[3] = __float2half(o.w * di);
        mir[(long)row * 64 + tid] = *reinterpret_cast<const uint2*>(h);
    }
}

// ---------------- launch ----------------
extern "C" void kernel_launch(void* const* d_in, const int* in_sizes, int n_in,
                              void* d_out, int out_size) {
    const float* x   = (const float*)d_in[0];
    const int*   ei  = (const int*)d_in[1];      // edge_index delivered as int32
    const float* lw  = (const float*)d_in[2];
    const float* lb  = (const float*)d_in[3];
    const float* wts = (const float*)d_in[4];
    float*       out = (float*)d_out;

    float* bufB;  __half *m0, *m1, *m2;
    __nv_bfloat16 *wh, *wl;
    int* degp;
    cudaGetSymbolAddress((void**)&bufB, g_bufB);
    cudaGetSymbolAddress((void**)&m0, g_m0);
    cudaGetSymbolAddress((void**)&m1, g_m1);
    cudaGetSymbolAddress((void**)&m2, g_m2);
    cudaGetSymbolAddress((void**)&wh, g_wh);
    cudaGetSymbolAddress((void**)&wl, g_wl);
    cudaGetSymbolAddress((void**)&degp, g_deg);

    // CSR degree + scan (dinv needed by GEMM epilogue)
    cudaMemsetAsync(degp, 0, N_NODES * sizeof(int));
    k_count<<<(E_EDGES / 4 + 255) / 256, 256>>>((const int4*)ei);
    k_scan<<<1, 1024>>>();

    // bf16 hi/lo split of W (x is split in-kernel)
    {
        int w4 = (OUT_CH * IN_CH) / 4;
        k_cvt<<<(w4 + 255) / 256, 256>>>((const float4*)lw, (uint2*)wh, (uint2*)wl, w4);
    }

    // out0 = x @ W^T + b -> d_out ; m0 = fp16(out0 * dinv)
    dim3 ggrid((N_NODES + GBM - 1) / GBM, OUT_CH / GBN);
    k_gemm_mma<<<ggrid, 128>>>(x, lb, out, m0);

    k_fill<<<(E_EDGES / 4 + 255) / 256, 256>>>((const int4*)ei);

    // k=0: bufB = out0 + w0 * A(out0); m1 = fp16(bufB * dinv)
    k_spmm<<<N_NODES, 64>>>((const uint2*)m0, (const float4*)out, wts, 0,
                            (float4*)bufB, (uint2*)m1);
    // k=1 hop 1: m2 = fp16(A(bufB) * dinv)   (fp32 output not needed)
    k_spmm<<<N_NODES, 64>>>((const uint2*)m1, nullptr, wts, 0,
                            nullptr, (uint2*)m2);
    // k=1 hop 2: d_out = bufB + w1 * A(prev)
    k_spmm<<<N_NODES, 64>>>((const uint2*)m2, (const float4*)bufB, wts, 1,
                            (float4*)out, nullptr);
}

// round 9
// speedup vs baseline: 1.8818x; 1.0002x over previous
#include <cuda_runtime.h>
#include <cuda_fp16.h>
#include <cuda_bf16.h>
#include <cstdint>

#define N_NODES 10000
#define E_EDGES 640000
#define IN_CH   512
#define OUT_CH  256

// ---------------- device-global scratch (no allocations allowed) ----------------
__device__ int    g_deg[N_NODES];
__device__ int    g_rowptr[N_NODES + 1];
__device__ int    g_cursor[N_NODES];
__device__ float  g_dinv[N_NODES];
__device__ int    g_col[E_EDGES];
__device__ float  g_bufB[N_NODES * OUT_CH];
// fp16 gather mirrors (pre-scaled by dinv[row])
__device__ __half g_m0[N_NODES * OUT_CH];
__device__ __half g_m1[N_NODES * OUT_CH];
__device__ __half g_m2[N_NODES * OUT_CH];
// bf16 hi/lo splits for the tensor-core GEMM
__device__ __nv_bfloat16 g_xh[N_NODES * IN_CH];
__device__ __nv_bfloat16 g_xl[N_NODES * IN_CH];
__device__ __nv_bfloat16 g_wh[OUT_CH * IN_CH];
__device__ __nv_bfloat16 g_wl[OUT_CH * IN_CH];

__device__ __forceinline__ uint32_t smem_u32(const void* p) {
    uint32_t a;
    asm("{ .reg .u64 t; cvta.to.shared.u64 t, %1; cvt.u32.u64 %0, t; }" : "=r"(a) : "l"(p));
    return a;
}

#define LDSM_X4(r0, r1, r2, r3, addr) \
    asm volatile("ldmatrix.sync.aligned.m8n8.x4.shared.b16 {%0,%1,%2,%3}, [%4];" \
                 : "=r"(r0), "=r"(r1), "=r"(r2), "=r"(r3) : "r"(addr))

#define MMA_BF16(d, a, b0, b1) \
    asm volatile( \
        "mma.sync.aligned.m16n8k16.row.col.f32.bf16.bf16.f32 " \
        "{%0,%1,%2,%3}, {%4,%5,%6,%7}, {%8,%9}, {%0,%1,%2,%3};" \
        : "+f"((d)[0]), "+f"((d)[1]), "+f"((d)[2]), "+f"((d)[3]) \
        : "r"((a)[0]), "r"((a)[1]), "r"((a)[2]), "r"((a)[3]), "r"(b0), "r"(b1))

// 16B async copy; src_sz = 16 (copy) or 0 (zero-fill)
#define CP_ASYNC16(dst, src, src_sz) \
    asm volatile("cp.async.cg.shared.global [%0], [%1], 16, %2;" \
                 :: "r"(dst), "l"(src), "r"(src_sz))
#define CP_COMMIT() asm volatile("cp.async.commit_group;" ::: "memory")
#define CP_WAIT1()  asm volatile("cp.async.wait_group 1;" ::: "memory")

// ---------------- CSR construction ----------------
// edge_index delivered as int32: ei[0..E) = row, ei[E..2E) = col
__global__ void k_count(const int4* __restrict__ ei4) {
    int i = blockIdx.x * blockDim.x + threadIdx.x;
    if (i < E_EDGES / 4) {
        int4 r = ei4[i];
        atomicAdd(&g_deg[min(max(r.x, 0), N_NODES - 1)], 1);
        atomicAdd(&g_deg[min(max(r.y, 0), N_NODES - 1)], 1);
        atomicAdd(&g_deg[min(max(r.z, 0), N_NODES - 1)], 1);
        atomicAdd(&g_deg[min(max(r.w, 0), N_NODES - 1)], 1);
    }
}

// 1-block register-blocked scan: 1024 threads x 10 elements each (10240 >= N)
#define SCAN_PER 10
__global__ __launch_bounds__(1024) void k_scan() {
    const int tid  = threadIdx.x;
    const int lane = tid & 31;
    const int wid  = tid >> 5;
    const int base = tid * SCAN_PER;

    int excl_local[SCAN_PER];
    int sum = 0;
    #pragma unroll
    for (int q = 0; q < SCAN_PER; q++) {
        int i = base + q;
        int v = (i < N_NODES) ? g_deg[i] : 0;
        excl_local[q] = sum;
        sum += v;
    }

    int inc = sum;
    #pragma unroll
    for (int off = 1; off < 32; off <<= 1) {
        int t = __shfl_up_sync(0xFFFFFFFFu, inc, off);
        if (lane >= off) inc += t;
    }

    __shared__ int wsum[32];
    if (lane == 31) wsum[wid] = inc;
    __syncthreads();
    if (wid == 0) {
        int v = wsum[lane];
        int wi = v;
        #pragma unroll
        for (int off = 1; off < 32; off <<= 1) {
            int t = __shfl_up_sync(0xFFFFFFFFu, wi, off);
            if (lane >= off) wi += t;
        }
        wsum[lane] = wi - v;
    }
    __syncthreads();

    const int offset = wsum[wid] + (inc - sum);

    #pragma unroll
    for (int q = 0; q < SCAN_PER; q++) {
        int i = base + q;
        if (i < N_NODES) {
            int excl = offset + excl_local[q];
            g_rowptr[i] = excl;
            g_cursor[i] = excl;
            int d = g_deg[i];
            g_dinv[i] = (d > 0) ? rsqrtf((float)d) : 0.0f;
        }
    }
    if (tid == 1023) g_rowptr[N_NODES] = offset + sum;
}

__global__ void k_fill(const int4* __restrict__ ei4) {
    int i = blockIdx.x * blockDim.x + threadIdx.x;
    if (i < E_EDGES / 4) {
        int4 r = ei4[i];
        int4 c = ei4[E_EDGES / 4 + i];
        int rr[4] = {r.x, r.y, r.z, r.w};
        int cc[4] = {c.x, c.y, c.z, c.w};
        #pragma unroll
        for (int q = 0; q < 4; q++) {
            int rv = min(max(rr[q], 0), N_NODES - 1);
            int cv = min(max(cc[q], 0), N_NODES - 1);
            int pos = atomicAdd(&g_cursor[rv], 1);
            if (pos >= 0 && pos < E_EDGES) g_col[pos] = cv;
        }
    }
}

// ---------------- bf16 hi/lo split conversion ----------------
__global__ void k_cvt(const float4* __restrict__ src,
                      uint2* __restrict__ hi, uint2* __restrict__ lo, int n4) {
    int i = blockIdx.x * blockDim.x + threadIdx.x;
    if (i < n4) {
        float4 v = src[i];
        __nv_bfloat16 h[4], l[4];
        h[0] = __float2bfloat16_rn(v.x); l[0] = __float2bfloat16_rn(v.x - __bfloat162float(h[0]));
        h[1] = __float2bfloat16_rn(v.y); l[1] = __float2bfloat16_rn(v.y - __bfloat162float(h[1]));
        h[2] = __float2bfloat16_rn(v.z); l[2] = __float2bfloat16_rn(v.z - __bfloat162float(h[2]));
        h[3] = __float2bfloat16_rn(v.w); l[3] = __float2bfloat16_rn(v.w - __bfloat162float(h[3]));
        hi[i] = *reinterpret_cast<const uint2*>(h);
        lo[i] = *reinterpret_cast<const uint2*>(l);
    }
}

// ---------------- Tensor-core GEMM (bf16x3, mma.sync + ldmatrix + cp.async) ----------------
// out[n,o] = sum_k x[n,k]*W[o,k] + b[o]; also mir = fp16(out*dinv[n]).
// CTA tile 128x64, 4 warps (warp 64x32), 3-stage cp.async pipeline, k16 chunks.
// 3 segment MMAs per chunk: Ah*Wh + Al*Wh + Ah*Wl.
#define GBM 128
#define GBN 64
#define SMSTRIDE 24           // bf16 per smem row (16 data + 8 pad)
#define STG_ELEM 9216         // (128+128+64+64)*24 bf16 per stage
#define STG_B    18432        // stage bytes
#define OFF_AL   (128 * SMSTRIDE)
#define OFF_WH   (256 * SMSTRIDE)
#define OFF_WL   (320 * SMSTRIDE)
#define GEMM_SMEM (3 * STG_B) // 55296 bytes

__global__ __launch_bounds__(128) void k_gemm_mma(const float* __restrict__ bias,
                                                  float* __restrict__ out,
                                                  __half* __restrict__ mir) {
    extern __shared__ __nv_bfloat16 smem[];
    const uint32_t sbase = smem_u32(smem);

    const int tid  = threadIdx.x;
    const int wid  = tid >> 5;
    const int lane = tid & 31;
    const int bm   = blockIdx.x * GBM;
    const int bn   = blockIdx.y * GBN;
    const int wm   = (wid & 1) * 64;
    const int wn   = (wid >> 1) * 32;
    const int q    = lane >> 2;
    const int s    = lane & 3;

    // ldmatrix lane geometry
    const int lg   = lane >> 3;
    const int l8   = lane & 7;
    const int arow = l8 + ((lg & 1) << 3);
    const int acol = (lg >> 1) << 3;
    const int brow = l8 + ((lg >> 1) << 3);
    const int bcol = (lg & 1) << 3;

    const uint32_t aHiB = sbase + ((wm + arow) * SMSTRIDE + acol) * 2;
    const uint32_t aLoB = aHiB + OFF_AL * 2;
    const uint32_t bHiB = sbase + OFF_WH * 2 + ((wn + brow) * SMSTRIDE + bcol) * 2;
    const uint32_t bLoB = bHiB + (OFF_WL - OFF_WH) * 2;
    const int MI_B = 16 * SMSTRIDE * 2;   // 768 bytes per 16-row step

    // cp.async loader geometry (per thread, per chunk): 6 x 16B
    //   A: chunks c = tid, tid+128 -> row = c>>1, kk = (c&1)*8   (hi and lo)
    //   W: row = tid>>1, kk = (tid&1)*8                          (hi and lo)
    const int ar0 = tid >> 1,           ak0 = (tid & 1) * 8;
    const int ar1 = (tid + 128) >> 1,   ak1 = ((tid + 128) & 1) * 8;
    const int wr  = tid >> 1,           wk  = (tid & 1) * 8;
    const int m0v = (bm + ar0 < N_NODES) ? 16 : 0;
    const int m1v = (bm + ar1 < N_NODES) ? 16 : 0;
    const long a0g = (long)min(bm + ar0, N_NODES - 1) * IN_CH;
    const long a1g = (long)min(bm + ar1, N_NODES - 1) * IN_CH;
    const long wg  = (long)(bn + wr) * IN_CH;
    const uint32_t dA0 = sbase + (ar0 * SMSTRIDE + ak0) * 2;
    const uint32_t dA1 = sbase + (ar1 * SMSTRIDE + ak1) * 2;
    const uint32_t dW  = sbase + (wr * SMSTRIDE + wk) * 2;

    #define ISSUE(ch, stg)                                                       \
    {                                                                            \
        const int k0_ = (ch) * 16;                                               \
        const uint32_t so_ = (stg) * STG_B;                                      \
        CP_ASYNC16(dA0 + so_,                 &g_xh[a0g + k0_ + ak0], m0v);       \
        CP_ASYNC16(dA1 + so_,                 &g_xh[a1g + k0_ + ak1], m1v);      \
        CP_ASYNC16(dA0 + so_ + OFF_AL * 2,    &g_xl[a0g + k0_ + ak0], m0v);      \
        CP_ASYNC16(dA1 + so_ + OFF_AL * 2,    &g_xl[a1g + k0_ + ak1], m1v);      \
        CP_ASYNC16(dW  + so_ + OFF_WH * 2,    &g_wh[wg + k0_ + wk], 16);         \
        CP_ASYNC16(dW  + so_ + OFF_WL * 2,    &g_wl[wg + k0_ + wk], 16);         \
        CP_COMMIT();                                                             \
    }

    float d[4][4][4];
    #pragma unroll
    for (int mi = 0; mi < 4; mi++)
        #pragma unroll
        for (int ni = 0; ni < 4; ni++)
            #pragma unroll
            for (int r = 0; r < 4; r++) d[mi][ni][r] = 0.0f;

    const int NCHUNK = IN_CH / 16;   // 32
    ISSUE(0, 0);
    ISSUE(1, 1);

    for (int ch = 0; ch < NCHUNK; ch++) {
        CP_WAIT1();
        __syncthreads();   // stage ch%3 ready everywhere; all warps past compute(ch-1)

        if (ch + 2 < NCHUNK) ISSUE(ch + 2, (ch + 2) % 3);

        const uint32_t so = (ch % 3) * STG_B;

        unsigned ah[4][4], al[4][4], bh[4][2], bl[4][2];
        #pragma unroll
        for (int mi = 0; mi < 4; mi++) {
            LDSM_X4(ah[mi][0], ah[mi][1], ah[mi][2], ah[mi][3], aHiB + so + mi * MI_B);
            LDSM_X4(al[mi][0], al[mi][1], al[mi][2], al[mi][3], aLoB + so + mi * MI_B);
        }
        #pragma unroll
        for (int p = 0; p < 2; p++) {
            unsigned t0, t1, t2, t3;
            LDSM_X4(t0, t1, t2, t3, bHiB + so + p * MI_B);
            bh[2 * p][0] = t0; bh[2 * p][1] = t1;
            bh[2 * p + 1][0] = t2; bh[2 * p + 1][1] = t3;
            LDSM_X4(t0, t1, t2, t3, bLoB + so + p * MI_B);
            bl[2 * p][0] = t0; bl[2 * p][1] = t1;
            bl[2 * p + 1][0] = t2; bl[2 * p + 1][1] = t3;
        }

        #pragma unroll
        for (int mi = 0; mi < 4; mi++) {
            #pragma unroll
            for (int ni = 0; ni < 4; ni++) MMA_BF16(d[mi][ni], ah[mi], bh[ni][0], bh[ni][1]);
            #pragma unroll
            for (int ni = 0; ni < 4; ni++) MMA_BF16(d[mi][ni], al[mi], bh[ni][0], bh[ni][1]);
            #pragma unroll
            for (int ni = 0; ni < 4; ni++) MMA_BF16(d[mi][ni], ah[mi], bl[ni][0], bl[ni][1]);
        }
    }
    #undef ISSUE

    // ---- epilogue: bias, fp32 out, fp16 mirror (scaled by dinv) ----
    float2 bv[4];
    #pragma unroll
    for (int ni = 0; ni < 4; ni++) {
        int c = bn + wn + ni * 8 + s * 2;
        bv[ni].x = bias[c];
        bv[ni].y = bias[c + 1];
    }

    #pragma unroll
    for (int mi = 0; mi < 4; mi++) {
        int r0 = bm + wm + mi * 16 + q;
        int r1 = r0 + 8;
        float di0 = (r0 < N_NODES) ? g_dinv[r0] : 0.0f;
        float di1 = (r1 < N_NODES) ? g_dinv[r1] : 0.0f;
        #pragma unroll
        for (int ni = 0; ni < 4; ni++) {
            int c = bn + wn + ni * 8 + s * 2;
            if (r0 < N_NODES) {
                float o0 = d[mi][ni][0] + bv[ni].x;
                float o1 = d[mi][ni][1] + bv[ni].y;
                *reinterpret_cast<float2*>(&out[(long)r0 * OUT_CH + c]) = make_float2(o0, o1);
                *reinterpret_cast<__half2*>(&mir[(long)r0 * OUT_CH + c]) =
                    __floats2half2_rn(o0 * di0, o1 * di0);
            }
            if (r1 < N_NODES) {
                float o0 = d[mi][ni][2] + bv[ni].x;
                float o1 = d[mi][ni][3] + bv[ni].y;
                *reinterpret_cast<float2*>(&out[(long)r1 * OUT_CH + c]) = make_float2(o0, o1);
                *reinterpret_cast<__half2*>(&mir[(long)r1 * OUT_CH + c]) =
                    __floats2half2_rn(o0 * di1, o1 * di1);
            }
        }
    }
}

// ---------------- SpMM gather: one row per 64-thread block ----------------
__global__ __launch_bounds__(64) void k_spmm(const uint2* __restrict__ h16,
                                             const float4* __restrict__ base4,
                                             const float* __restrict__ wptr,
                                             int widx,
                                             float4* __restrict__ out4,
                                             uint2* __restrict__ mir) {
    __shared__ int scol[256];

    const int row = blockIdx.x;
    const int tid = threadIdx.x;        // 0..63, owns 4 channels
    const int s   = g_rowptr[row];
    const int e   = g_rowptr[row + 1];

    float4 acc = make_float4(0.f, 0.f, 0.f, 0.f);

    for (int bs = s; bs < e; bs += 256) {
        int cnt = min(256, e - bs);
        for (int j = tid; j < cnt; j += 64) scol[j] = g_col[bs + j];
        __syncthreads();
        int j = 0;
        for (; j + 4 <= cnt; j += 4) {
            int c0 = scol[j + 0], c1 = scol[j + 1], c2 = scol[j + 2], c3 = scol[j + 3];
            uint2 u0 = h16[(long)c0 * 64 + tid];
            uint2 u1 = h16[(long)c1 * 64 + tid];
            uint2 u2 = h16[(long)c2 * 64 + tid];
            uint2 u3 = h16[(long)c3 * 64 + tid];
            float2 a0 = __half22float2(*reinterpret_cast<const __half2*>(&u0.x));
            float2 b0 = __half22float2(*reinterpret_cast<const __half2*>(&u0.y));
            float2 a1 = __half22float2(*reinterpret_cast<const __half2*>(&u1.x));
            float2 b1 = __half22float2(*reinterpret_cast<const __half2*>(&u1.y));
            float2 a2 = __half22float2(*reinterpret_cast<const __half2*>(&u2.x));
            float2 b2 = __half22float2(*reinterpret_cast<const __half2*>(&u2.y));
            float2 a3 = __half22float2(*reinterpret_cast<const __half2*>(&u3.x));
            float2 b3 = __half22float2(*reinterpret_cast<const __half2*>(&u3.y));
            acc.x += a0.x + a1.x + a2.x + a3.x;
            acc.y += a0.y + a1.y + a2.y + a3.y;
            acc.z += b0.x + b1.x + b2.x + b3.x;
            acc.w += b0.y + b1.y + b2.y + b3.y;
        }
        for (; j < cnt; j++) {
            uint2 u = h16[(long)scol[j] * 64 + tid];
            float2 a = __half22float2(*reinterpret_cast<const __half2*>(&u.x));
            float2 b = __half22float2(*reinterpret_cast<const __half2*>(&u.y));
            acc.x += a.x; acc.y += a.y; acc.z += b.x; acc.w += b.y;
        }
        __syncthreads();
    }

    const float di = g_dinv[row];
    float4 r;
    r.x = di * acc.x; r.y = di * acc.y; r.z = di * acc.z; r.w = di * acc.w;

    float4 o;
    if (base4 != nullptr) {
        float wk = wptr[widx];
        float4 bv = base4[(long)row * 64 + tid];
        o.x = bv.x + wk * r.x;
        o.y = bv.y + wk * r.y;
        o.z = bv.z + wk * r.z;
        o.w = bv.w + wk * r.w;
    } else {
        o = r;
    }
    if (out4 != nullptr) out4[(long)row * 64 + tid] = o;
    if (mir != nullptr) {
        __half h[4];
        h[0] = __float2half(o.x * di);
        h[1] = __float2half(o.y * di);
        h[2] = __float2half(o.z * di);
        h[3] = __float2half(o.w * di);
        mir[(long)row * 64 + tid] = *reinterpret_cast<const uint2*>(h);
    }
}

// ---------------- launch ----------------
extern "C" void kernel_launch(void* const* d_in, const int* in_sizes, int n_in,
                              void* d_out, int out_size) {
    const float* x   = (const float*)d_in[0];
    const int*   ei  = (const int*)d_in[1];      // edge_index delivered as int32
    const float* lw  = (const float*)d_in[2];
    const float* lb  = (const float*)d_in[3];
    const float* wts = (const float*)d_in[4];
    float*       out = (float*)d_out;

    float* bufB;  __half *m0, *m1, *m2;
    __nv_bfloat16 *xh, *xl, *wh, *wl;
    int* degp;
    cudaGetSymbolAddress((void**)&bufB, g_bufB);
    cudaGetSymbolAddress((void**)&m0, g_m0);
    cudaGetSymbolAddress((void**)&m1, g_m1);
    cudaGetSymbolAddress((void**)&m2, g_m2);
    cudaGetSymbolAddress((void**)&xh, g_xh);
    cudaGetSymbolAddress((void**)&xl, g_xl);
    cudaGetSymbolAddress((void**)&wh, g_wh);
    cudaGetSymbolAddress((void**)&wl, g_wl);
    cudaGetSymbolAddress((void**)&degp, g_deg);

    cudaFuncSetAttribute(k_gemm_mma, cudaFuncAttributeMaxDynamicSharedMemorySize, GEMM_SMEM);

    // CSR degree + scan (dinv needed by GEMM epilogue)
    cudaMemsetAsync(degp, 0, N_NODES * sizeof(int));
    k_count<<<(E_EDGES / 4 + 255) / 256, 256>>>((const int4*)ei);
    k_scan<<<1, 1024>>>();

    // bf16 hi/lo splits of x and W
    {
        int n4 = (N_NODES * IN_CH) / 4;
        k_cvt<<<(n4 + 255) / 256, 256>>>((const float4*)x, (uint2*)xh, (uint2*)xl, n4);
        int w4 = (OUT_CH * IN_CH) / 4;
        k_cvt<<<(w4 + 255) / 256, 256>>>((const float4*)lw, (uint2*)wh, (uint2*)wl, w4);
    }

    // out0 = x @ W^T + b -> d_out ; m0 = fp16(out0 * dinv)
    dim3 ggrid((N_NODES + GBM - 1) / GBM, OUT_CH / GBN);
    k_gemm_mma<<<ggrid, 128, GEMM_SMEM>>>(lb, out, m0);

    k_fill<<<(E_EDGES / 4 + 255) / 256, 256>>>((const int4*)ei);

    // k=0: bufB = out0 + w0 * A(out0); m1 = fp16(bufB * dinv)
    k_spmm<<<N_NODES, 64>>>((const uint2*)m0, (const float4*)out, wts, 0,
                            (float4*)bufB, (uint2*)m1);
    // k=1 hop 1: m2 = fp16(A(bufB) * dinv)   (fp32 output not needed)
    k_spmm<<<N_NODES, 64>>>((const uint2*)m1, nullptr, wts, 0,
                            nullptr, (uint2*)m2);
    // k=1 hop 2: d_out = bufB + w1 * A(prev)
    k_spmm<<<N_NODES, 64>>>((const uint2*)m2, (const float4*)bufB, wts, 1,
                            (float4*)out, nullptr);
}

// round 10
// speedup vs baseline: 2.1110x; 1.1218x over previous
#include <cuda_runtime.h>
#include <cuda_fp16.h>
#include <cuda_bf16.h>
#include <cstdint>

#define N_NODES 10000
#define E_EDGES 640000
#define IN_CH   512
#define OUT_CH  256

// ---------------- device-global scratch (no allocations allowed) ----------------
__device__ int    g_deg[N_NODES];
__device__ int    g_rowptr[N_NODES + 1];
__device__ int    g_cursor[N_NODES];
__device__ float  g_dinv[N_NODES];
__device__ int    g_col[E_EDGES];
__device__ float  g_bufB[N_NODES * OUT_CH];
// fp16 gather mirrors (pre-scaled by dinv[row])
__device__ __half g_m0[N_NODES * OUT_CH];
__device__ __half g_m1[N_NODES * OUT_CH];
__device__ __half g_m2[N_NODES * OUT_CH];
// bf16 hi/lo splits for the tensor-core GEMM
__device__ __nv_bfloat16 g_xh[N_NODES * IN_CH];
__device__ __nv_bfloat16 g_xl[N_NODES * IN_CH];
__device__ __nv_bfloat16 g_wh[OUT_CH * IN_CH];
__device__ __nv_bfloat16 g_wl[OUT_CH * IN_CH];

__device__ __forceinline__ uint32_t smem_u32(const void* p) {
    uint32_t a;
    asm("{ .reg .u64 t; cvta.to.shared.u64 t, %1; cvt.u32.u64 %0, t; }" : "=r"(a) : "l"(p));
    return a;
}

#define LDSM_X4(r0, r1, r2, r3, addr) \
    asm volatile("ldmatrix.sync.aligned.m8n8.x4.shared.b16 {%0,%1,%2,%3}, [%4];" \
                 : "=r"(r0), "=r"(r1), "=r"(r2), "=r"(r3) : "r"(addr))

#define MMA_BF16(d, a, b0, b1) \
    asm volatile( \
        "mma.sync.aligned.m16n8k16.row.col.f32.bf16.bf16.f32 " \
        "{%0,%1,%2,%3}, {%4,%5,%6,%7}, {%8,%9}, {%0,%1,%2,%3};" \
        : "+f"((d)[0]), "+f"((d)[1]), "+f"((d)[2]), "+f"((d)[3]) \
        : "r"((a)[0]), "r"((a)[1]), "r"((a)[2]), "r"((a)[3]), "r"(b0), "r"(b1))

// 16B async copy; src_sz = 16 (copy) or 0 (zero-fill)
#define CP_ASYNC16(dst, src, src_sz) \
    asm volatile("cp.async.cg.shared.global [%0], [%1], 16, %2;" \
                 :: "r"(dst), "l"(src), "r"(src_sz))
#define CP_COMMIT() asm volatile("cp.async.commit_group;" ::: "memory")
#define CP_WAIT1()  asm volatile("cp.async.wait_group 1;" ::: "memory")

// ---------------- CSR construction ----------------
// edge_index delivered as int32: ei[0..E) = row, ei[E..2E) = col
__global__ void k_count(const int4* __restrict__ ei4) {
    int i = blockIdx.x * blockDim.x + threadIdx.x;
    if (i < E_EDGES / 4) {
        int4 r = ei4[i];
        atomicAdd(&g_deg[min(max(r.x, 0), N_NODES - 1)], 1);
        atomicAdd(&g_deg[min(max(r.y, 0), N_NODES - 1)], 1);
        atomicAdd(&g_deg[min(max(r.z, 0), N_NODES - 1)], 1);
        atomicAdd(&g_deg[min(max(r.w, 0), N_NODES - 1)], 1);
    }
}

// 1-block register-blocked scan: 1024 threads x 10 elements each (10240 >= N)
#define SCAN_PER 10
__global__ __launch_bounds__(1024) void k_scan() {
    const int tid  = threadIdx.x;
    const int lane = tid & 31;
    const int wid  = tid >> 5;
    const int base = tid * SCAN_PER;

    int excl_local[SCAN_PER];
    int sum = 0;
    #pragma unroll
    for (int q = 0; q < SCAN_PER; q++) {
        int i = base + q;
        int v = (i < N_NODES) ? g_deg[i] : 0;
        excl_local[q] = sum;
        sum += v;
    }

    int inc = sum;
    #pragma unroll
    for (int off = 1; off < 32; off <<= 1) {
        int t = __shfl_up_sync(0xFFFFFFFFu, inc, off);
        if (lane >= off) inc += t;
    }

    __shared__ int wsum[32];
    if (lane == 31) wsum[wid] = inc;
    __syncthreads();
    if (wid == 0) {
        int v = wsum[lane];
        int wi = v;
        #pragma unroll
        for (int off = 1; off < 32; off <<= 1) {
            int t = __shfl_up_sync(0xFFFFFFFFu, wi, off);
            if (lane >= off) wi += t;
        }
        wsum[lane] = wi - v;
    }
    __syncthreads();

    const int offset = wsum[wid] + (inc - sum);

    #pragma unroll
    for (int q = 0; q < SCAN_PER; q++) {
        int i = base + q;
        if (i < N_NODES) {
            int excl = offset + excl_local[q];
            g_rowptr[i] = excl;
            g_cursor[i] = excl;
            int d = g_deg[i];
            g_dinv[i] = (d > 0) ? rsqrtf((float)d) : 0.0f;
        }
    }
    if (tid == 1023) g_rowptr[N_NODES] = offset + sum;
}

__global__ void k_fill(const int4* __restrict__ ei4) {
    int i = blockIdx.x * blockDim.x + threadIdx.x;
    if (i < E_EDGES / 4) {
        int4 r = ei4[i];
        int4 c = ei4[E_EDGES / 4 + i];
        int rr[4] = {r.x, r.y, r.z, r.w};
        int cc[4] = {c.x, c.y, c.z, c.w};
        #pragma unroll
        for (int q = 0; q < 4; q++) {
            int rv = min(max(rr[q], 0), N_NODES - 1);
            int cv = min(max(cc[q], 0), N_NODES - 1);
            int pos = atomicAdd(&g_cursor[rv], 1);
            if (pos >= 0 && pos < E_EDGES) g_col[pos] = cv;
        }
    }
}

// ---------------- bf16 hi/lo split conversion ----------------
__global__ void k_cvt(const float4* __restrict__ src,
                      uint2* __restrict__ hi, uint2* __restrict__ lo, int n4) {
    int i = blockIdx.x * blockDim.x + threadIdx.x;
    if (i < n4) {
        float4 v = src[i];
        __nv_bfloat16 h[4], l[4];
        h[0] = __float2bfloat16_rn(v.x); l[0] = __float2bfloat16_rn(v.x - __bfloat162float(h[0]));
        h[1] = __float2bfloat16_rn(v.y); l[1] = __float2bfloat16_rn(v.y - __bfloat162float(h[1]));
        h[2] = __float2bfloat16_rn(v.z); l[2] = __float2bfloat16_rn(v.z - __bfloat162float(h[2]));
        h[3] = __float2bfloat16_rn(v.w); l[3] = __float2bfloat16_rn(v.w - __bfloat162float(h[3]));
        hi[i] = *reinterpret_cast<const uint2*>(h);
        lo[i] = *reinterpret_cast<const uint2*>(l);
    }
}

// ---------------- Tensor-core GEMM (bf16x3, mma.sync + ldmatrix + cp.async) ----------------
// out[n,o] = sum_k x[n,k]*W[o,k] + b[o]; also mir = fp16(out*dinv[n]).
// CTA tile 128x64, 8 warps (warp tile 32x32), 3-stage cp.async pipeline, k16 chunks.
// 3 segment MMAs per chunk: Ah*Wh + Al*Wh + Ah*Wl.
#define GBM 128
#define GBN 64
#define SMSTRIDE 24           // bf16 per smem row (16 data + 8 pad)
#define STG_B    18432        // stage bytes: (128+128+64+64)*24*2
#define OFF_AL   (128 * SMSTRIDE)
#define OFF_WH   (256 * SMSTRIDE)
#define OFF_WL   (320 * SMSTRIDE)
#define GEMM_SMEM (3 * STG_B) // 55296 bytes

__global__ __launch_bounds__(256) void k_gemm_mma(const float* __restrict__ bias,
                                                  float* __restrict__ out,
                                                  __half* __restrict__ mir) {
    extern __shared__ __nv_bfloat16 smem[];
    const uint32_t sbase = smem_u32(smem);

    const int tid  = threadIdx.x;
    const int wid  = tid >> 5;          // 0..7
    const int lane = tid & 31;
    const int bm   = blockIdx.x * GBM;
    const int bn   = blockIdx.y * GBN;
    const int wm   = (wid & 3) * 32;    // 0,32,64,96
    const int wn   = (wid >> 2) * 32;   // 0,32
    const int q    = lane >> 2;
    const int s    = lane & 3;

    // ldmatrix lane geometry
    const int lg   = lane >> 3;
    const int l8   = lane & 7;
    const int arow = l8 + ((lg & 1) << 3);
    const int acol = (lg >> 1) << 3;
    const int brow = l8 + ((lg >> 1) << 3);
    const int bcol = (lg & 1) << 3;

    const uint32_t aHiB = sbase + ((wm + arow) * SMSTRIDE + acol) * 2;
    const uint32_t aLoB = aHiB + OFF_AL * 2;
    const uint32_t bHiB = sbase + OFF_WH * 2 + ((wn + brow) * SMSTRIDE + bcol) * 2;
    const uint32_t bLoB = bHiB + (OFF_WL - OFF_WH) * 2;
    const int MI_B = 16 * SMSTRIDE * 2;   // 768 bytes per 16-row step

    // cp.async loader geometry: A = 256 x 16B chunks (1/thread, hi+lo);
    // W = 128 x 16B chunks (threads 0..127, hi+lo)
    const int ar = tid >> 1,  ak = (tid & 1) * 8;
    const int mv = (bm + ar < N_NODES) ? 16 : 0;
    const long ag = (long)min(bm + ar, N_NODES - 1) * IN_CH;
    const uint32_t dA = sbase + (ar * SMSTRIDE + ak) * 2;
    const int wr = tid >> 1,  wk = (tid & 1) * 8;   // valid for tid<128
    const long wg = (long)(bn + wr) * IN_CH;
    const uint32_t dW = sbase + OFF_WH * 2 + (wr * SMSTRIDE + wk) * 2;

    #define ISSUE(ch, stg)                                                       \
    {                                                                            \
        const int k0_ = (ch) * 16;                                               \
        const uint32_t so_ = (stg) * STG_B;                                      \
        CP_ASYNC16(dA + so_,              &g_xh[ag + k0_ + ak], mv);             \
        CP_ASYNC16(dA + so_ + OFF_AL * 2, &g_xl[ag + k0_ + ak], mv);             \
        if (tid < 128) {                                                         \
            CP_ASYNC16(dW + so_,                          &g_wh[wg + k0_ + wk], 16); \
            CP_ASYNC16(dW + so_ + (OFF_WL - OFF_WH) * 2,  &g_wl[wg + k0_ + wk], 16); \
        }                                                                        \
        CP_COMMIT();                                                             \
    }

    float d[2][4][4];
    #pragma unroll
    for (int mi = 0; mi < 2; mi++)
        #pragma unroll
        for (int ni = 0; ni < 4; ni++)
            #pragma unroll
            for (int r = 0; r < 4; r++) d[mi][ni][r] = 0.0f;

    const int NCHUNK = IN_CH / 16;   // 32
    ISSUE(0, 0);
    ISSUE(1, 1);

    for (int ch = 0; ch < NCHUNK; ch++) {
        CP_WAIT1();
        __syncthreads();   // stage ch%3 ready everywhere; all warps past compute(ch-1)

        if (ch + 2 < NCHUNK) ISSUE(ch + 2, (ch + 2) % 3);

        const uint32_t so = (ch % 3) * STG_B;

        unsigned ah[2][4], al[2][4], bh[4][2], bl[4][2];
        #pragma unroll
        for (int mi = 0; mi < 2; mi++) {
            LDSM_X4(ah[mi][0], ah[mi][1], ah[mi][2], ah[mi][3], aHiB + so + mi * MI_B);
            LDSM_X4(al[mi][0], al[mi][1], al[mi][2], al[mi][3], aLoB + so + mi * MI_B);
        }
        #pragma unroll
        for (int p = 0; p < 2; p++) {
            unsigned t0, t1, t2, t3;
            LDSM_X4(t0, t1, t2, t3, bHiB + so + p * MI_B);
            bh[2 * p][0] = t0; bh[2 * p][1] = t1;
            bh[2 * p + 1][0] = t2; bh[2 * p + 1][1] = t3;
            LDSM_X4(t0, t1, t2, t3, bLoB + so + p * MI_B);
            bl[2 * p][0] = t0; bl[2 * p][1] = t1;
            bl[2 * p + 1][0] = t2; bl[2 * p + 1][1] = t3;
        }

        #pragma unroll
        for (int mi = 0; mi < 2; mi++) {
            #pragma unroll
            for (int ni = 0; ni < 4; ni++) MMA_BF16(d[mi][ni], ah[mi], bh[ni][0], bh[ni][1]);
            #pragma unroll
            for (int ni = 0; ni < 4; ni++) MMA_BF16(d[mi][ni], al[mi], bh[ni][0], bh[ni][1]);
            #pragma unroll
            for (int ni = 0; ni < 4; ni++) MMA_BF16(d[mi][ni], ah[mi], bl[ni][0], bl[ni][1]);
        }
    }
    #undef ISSUE

    // ---- epilogue: bias, fp32 out, fp16 mirror (scaled by dinv) ----
    float2 bv[4];
    #pragma unroll
    for (int ni = 0; ni < 4; ni++) {
        int c = bn + wn + ni * 8 + s * 2;
        bv[ni].x = bias[c];
        bv[ni].y = bias[c + 1];
    }

    #pragma unroll
    for (int mi = 0; mi < 2; mi++) {
        int r0 = bm + wm + mi * 16 + q;
        int r1 = r0 + 8;
        float di0 = (r0 < N_NODES) ? g_dinv[r0] : 0.0f;
        float di1 = (r1 < N_NODES) ? g_dinv[r1] : 0.0f;
        #pragma unroll
        for (int ni = 0; ni < 4; ni++) {
            int c = bn + wn + ni * 8 + s * 2;
            if (r0 < N_NODES) {
                float o0 = d[mi][ni][0] + bv[ni].x;
                float o1 = d[mi][ni][1] + bv[ni].y;
                *reinterpret_cast<float2*>(&out[(long)r0 * OUT_CH + c]) = make_float2(o0, o1);
                *reinterpret_cast<__half2*>(&mir[(long)r0 * OUT_CH + c]) =
                    __floats2half2_rn(o0 * di0, o1 * di0);
            }
            if (r1 < N_NODES) {
                float o0 = d[mi][ni][2] + bv[ni].x;
                float o1 = d[mi][ni][3] + bv[ni].y;
                *reinterpret_cast<float2*>(&out[(long)r1 * OUT_CH + c]) = make_float2(o0, o1);
                *reinterpret_cast<__half2*>(&mir[(long)r1 * OUT_CH + c]) =
                    __floats2half2_rn(o0 * di1, o1 * di1);
            }
        }
    }
}

// ---------------- SpMM gather: one row per 64-thread block ----------------
__global__ __launch_bounds__(64) void k_spmm(const uint2* __restrict__ h16,
                                             const float4* __restrict__ base4,
                                             const float* __restrict__ wptr,
                                             int widx,
                                             float4* __restrict__ out4,
                                             uint2* __restrict__ mir) {
    __shared__ int scol[256];

    const int row = blockIdx.x;
    const int tid = threadIdx.x;        // 0..63, owns 4 channels
    const int s   = g_rowptr[row];
    const int e   = g_rowptr[row + 1];

    float4 acc = make_float4(0.f, 0.f, 0.f, 0.f);

    for (int bs = s; bs < e; bs += 256) {
        int cnt = min(256, e - bs);
        for (int j = tid; j < cnt; j += 64) scol[j] = g_col[bs + j];
        __syncthreads();
        int j = 0;
        for (; j + 4 <= cnt; j += 4) {
            int c0 = scol[j + 0], c1 = scol[j + 1], c2 = scol[j + 2], c3 = scol[j + 3];
            uint2 u0 = h16[(long)c0 * 64 + tid];
            uint2 u1 = h16[(long)c1 * 64 + tid];
            uint2 u2 = h16[(long)c2 * 64 + tid];
            uint2 u3 = h16[(long)c3 * 64 + tid];
            float2 a0 = __half22float2(*reinterpret_cast<const __half2*>(&u0.x));
            float2 b0 = __half22float2(*reinterpret_cast<const __half2*>(&u0.y));
            float2 a1 = __half22float2(*reinterpret_cast<const __half2*>(&u1.x));
            float2 b1 = __half22float2(*reinterpret_cast<const __half2*>(&u1.y));
            float2 a2 = __half22float2(*reinterpret_cast<const __half2*>(&u2.x));
            float2 b2 = __half22float2(*reinterpret_cast<const __half2*>(&u2.y));
            float2 a3 = __half22float2(*reinterpret_cast<const __half2*>(&u3.x));
            float2 b3 = __half22float2(*reinterpret_cast<const __half2*>(&u3.y));
            acc.x += a0.x + a1.x + a2.x + a3.x;
            acc.y += a0.y + a1.y + a2.y + a3.y;
            acc.z += b0.x + b1.x + b2.x + b3.x;
            acc.w += b0.y + b1.y + b2.y + b3.y;
        }
        for (; j < cnt; j++) {
            uint2 u = h16[(long)scol[j] * 64 + tid];
            float2 a = __half22float2(*reinterpret_cast<const __half2*>(&u.x));
            float2 b = __half22float2(*reinterpret_cast<const __half2*>(&u.y));
            acc.x += a.x; acc.y += a.y; acc.z += b.x; acc.w += b.y;
        }
        __syncthreads();
    }

    const float di = g_dinv[row];
    float4 r;
    r.x = di * acc.x; r.y = di * acc.y; r.z = di * acc.z; r.w = di * acc.w;

    float4 o;
    if (base4 != nullptr) {
        float wk = wptr[widx];
        float4 bv = base4[(long)row * 64 + tid];
        o.x = bv.x + wk * r.x;
        o.y = bv.y + wk * r.y;
        o.z = bv.z + wk * r.z;
        o.w = bv.w + wk * r.w;
    } else {
        o = r;
    }
    if (out4 != nullptr) out4[(long)row * 64 + tid] = o;
    if (mir != nullptr) {
        __half h[4];
        h[0] = __float2half(o.x * di);
        h[1] = __float2half(o.y * di);
        h[2] = __float2half(o.z * di);
        h[3] = __float2half(o.w * di);
        mir[(long)row * 64 + tid] = *reinterpret_cast<const uint2*>(h);
    }
}

// ---------------- launch ----------------
extern "C" void kernel_launch(void* const* d_in, const int* in_sizes, int n_in,
                              void* d_out, int out_size) {
    const float* x   = (const float*)d_in[0];
    const int*   ei  = (const int*)d_in[1];      // edge_index delivered as int32
    const float* lw  = (const float*)d_in[2];
    const float* lb  = (const float*)d_in[3];
    const float* wts = (const float*)d_in[4];
    float*       out = (float*)d_out;

    float* bufB;  __half *m0, *m1, *m2;
    __nv_bfloat16 *xh, *xl, *wh, *wl;
    int* degp;
    cudaGetSymbolAddress((void**)&bufB, g_bufB);
    cudaGetSymbolAddress((void**)&m0, g_m0);
    cudaGetSymbolAddress((void**)&m1, g_m1);
    cudaGetSymbolAddress((void**)&m2, g_m2);
    cudaGetSymbolAddress((void**)&xh, g_xh);
    cudaGetSymbolAddress((void**)&xl, g_xl);
    cudaGetSymbolAddress((void**)&wh, g_wh);
    cudaGetSymbolAddress((void**)&wl, g_wl);
    cudaGetSymbolAddress((void**)&degp, g_deg);

    // one-time infra (created on the non-capturing correctness call)
    static cudaStream_t s2 = nullptr;
    static cudaEvent_t evStart, evScan, evCvt, evFill;
    if (s2 == nullptr) {
        cudaStreamCreateWithFlags(&s2, cudaStreamNonBlocking);
        cudaEventCreateWithFlags(&evStart, cudaEventDisableTiming);
        cudaEventCreateWithFlags(&evScan,  cudaEventDisableTiming);
        cudaEventCreateWithFlags(&evCvt,   cudaEventDisableTiming);
        cudaEventCreateWithFlags(&evFill,  cudaEventDisableTiming);
        cudaFuncSetAttribute(k_gemm_mma, cudaFuncAttributeMaxDynamicSharedMemorySize, GEMM_SMEM);
    }

    // fork side stream from the main (captured) stream
    cudaEventRecord(evStart, 0);
    cudaStreamWaitEvent(s2, evStart, 0);

    // main stream: CSR degree + scan (produces dinv + cursor)
    cudaMemsetAsync(degp, 0, N_NODES * sizeof(int), 0);
    k_count<<<(E_EDGES / 4 + 255) / 256, 256>>>((const int4*)ei);
    k_scan<<<1, 1024>>>();
    cudaEventRecord(evScan, 0);

    // side stream: bf16 splits (independent), then fill (needs scan's cursor)
    {
        int n4 = (N_NODES * IN_CH) / 4;
        k_cvt<<<(n4 + 255) / 256, 256, 0, s2>>>((const float4*)x, (uint2*)xh, (uint2*)xl, n4);
        int w4 = (OUT_CH * IN_CH) / 4;
        k_cvt<<<(w4 + 255) / 256, 256, 0, s2>>>((const float4*)lw, (uint2*)wh, (uint2*)wl, w4);
    }
    cudaEventRecord(evCvt, s2);
    cudaStreamWaitEvent(s2, evScan, 0);
    k_fill<<<(E_EDGES / 4 + 255) / 256, 256, 0, s2>>>((const int4*)ei);
    cudaEventRecord(evFill, s2);

    // main stream: GEMM (needs cvt + scan); fill overlaps with it on s2
    cudaStreamWaitEvent(0, evCvt, 0);
    dim3 ggrid((N_NODES + GBM - 1) / GBM, OUT_CH / GBN);
    k_gemm_mma<<<ggrid, 256, GEMM_SMEM>>>(lb, out, m0);

    // join fill before SpMM chain
    cudaStreamWaitEvent(0, evFill, 0);

    // k=0: bufB = out0 + w0 * A(out0); m1 = fp16(bufB * dinv)
    k_spmm<<<N_NODES, 64>>>((const uint2*)m0, (const float4*)out, wts, 0,
                            (float4*)bufB, (uint2*)m1);
    // k=1 hop 1: m2 = fp16(A(bufB) * dinv)   (fp32 output not needed)
    k_spmm<<<N_NODES, 64>>>((const uint2*)m1, nullptr, wts, 0,
                            nullptr, (uint2*)m2);
    // k=1 hop 2: d_out = bufB + w1 * A(prev)
    k_spmm<<<N_NODES, 64>>>((const uint2*)m2, (const float4*)bufB, wts, 1,
                            (float4*)out, nullptr);
}

// round 13
// speedup vs baseline: 2.1240x; 1.0062x over previous
#include <cuda_runtime.h>
#include <cuda_fp16.h>
#include <cuda_bf16.h>
#include <cstdint>

#define N_NODES 10000
#define E_EDGES 640000
#define IN_CH   512
#define OUT_CH  256

// ---------------- device-global scratch (no allocations allowed) ----------------
__device__ int    g_deg[N_NODES];
__device__ int    g_rowptr[N_NODES + 1];
__device__ int    g_cursor[N_NODES];
__device__ float  g_dinv[N_NODES];
__device__ int    g_col[E_EDGES];
__device__ float  g_bufB[N_NODES * OUT_CH];
// fp16 gather mirrors (pre-scaled by dinv[row])
__device__ __half g_m0[N_NODES * OUT_CH];
__device__ __half g_m1[N_NODES * OUT_CH];
__device__ __half g_m2[N_NODES * OUT_CH];
// bf16 hi/lo splits for the tensor-core GEMM
__device__ __nv_bfloat16 g_xh[N_NODES * IN_CH];
__device__ __nv_bfloat16 g_xl[N_NODES * IN_CH];
__device__ __nv_bfloat16 g_wh[OUT_CH * IN_CH];
__device__ __nv_bfloat16 g_wl[OUT_CH * IN_CH];

__device__ __forceinline__ uint32_t smem_u32(const void* p) {
    uint32_t a;
    asm("{ .reg .u64 t; cvta.to.shared.u64 t, %1; cvt.u32.u64 %0, t; }" : "=r"(a) : "l"(p));
    return a;
}

#define LDSM_X4(r0, r1, r2, r3, addr) \
    asm volatile("ldmatrix.sync.aligned.m8n8.x4.shared.b16 {%0,%1,%2,%3}, [%4];" \
                 : "=r"(r0), "=r"(r1), "=r"(r2), "=r"(r3) : "r"(addr))

#define MMA_BF16(d, a, b0, b1) \
    asm volatile( \
        "mma.sync.aligned.m16n8k16.row.col.f32.bf16.bf16.f32 " \
        "{%0,%1,%2,%3}, {%4,%5,%6,%7}, {%8,%9}, {%0,%1,%2,%3};" \
        : "+f"((d)[0]), "+f"((d)[1]), "+f"((d)[2]), "+f"((d)[3]) \
        : "r"((a)[0]), "r"((a)[1]), "r"((a)[2]), "r"((a)[3]), "r"(b0), "r"(b1))

// 16B async copy; src_sz = 16 (copy) or 0 (zero-fill)
#define CP_ASYNC16(dst, src, src_sz) \
    asm volatile("cp.async.cg.shared.global [%0], [%1], 16, %2;" \
                 :: "r"(dst), "l"(src), "r"(src_sz))
#define CP_COMMIT() asm volatile("cp.async.commit_group;" ::: "memory")
#define CP_WAIT1()  asm volatile("cp.async.wait_group 1;" ::: "memory")

// ---------------- CSR construction ----------------
// edge_index delivered as int32: ei[0..E) = row, ei[E..2E) = col
// Shared-memory histogram count: 40 blocks x 16000 edges; smem atomics then
// one global add per nonzero counter (400k global atomics vs 2.56M direct).
#define CNT_BLOCKS 40
#define CNT_I4_PER_BLOCK (E_EDGES / 4 / CNT_BLOCKS)   // 4000

__global__ __launch_bounds__(256) void k_count(const int4* __restrict__ ei4) {
    __shared__ int h[N_NODES];
    const int tid = threadIdx.x;
    for (int i = tid; i < N_NODES; i += 256) h[i] = 0;
    __syncthreads();

    const int base = blockIdx.x * CNT_I4_PER_BLOCK;
    for (int i = base + tid; i < base + CNT_I4_PER_BLOCK; i += 256) {
        int4 r = ei4[i];
        atomicAdd(&h[min(max(r.x, 0), N_NODES - 1)], 1);
        atomicAdd(&h[min(max(r.y, 0), N_NODES - 1)], 1);
        atomicAdd(&h[min(max(r.z, 0), N_NODES - 1)], 1);
        atomicAdd(&h[min(max(r.w, 0), N_NODES - 1)], 1);
    }
    __syncthreads();

    for (int i = tid; i < N_NODES; i += 256) {
        int v = h[i];
        if (v) atomicAdd(&g_deg[i], v);
    }
}

// 1-block register-blocked scan: 1024 threads x 10 elements each (10240 >= N)
#define SCAN_PER 10
__global__ __launch_bounds__(1024) void k_scan() {
    const int tid  = threadIdx.x;
    const int lane = tid & 31;
    const int wid  = tid >> 5;
    const int base = tid * SCAN_PER;

    int excl_local[SCAN_PER];
    int sum = 0;
    #pragma unroll
    for (int q = 0; q < SCAN_PER; q++) {
        int i = base + q;
        int v = (i < N_NODES) ? g_deg[i] : 0;
        excl_local[q] = sum;
        sum += v;
    }

    int inc = sum;
    #pragma unroll
    for (int off = 1; off < 32; off <<= 1) {
        int t = __shfl_up_sync(0xFFFFFFFFu, inc, off);
        if (lane >= off) inc += t;
    }

    __shared__ int wsum[32];
    if (lane == 31) wsum[wid] = inc;
    __syncthreads();
    if (wid == 0) {
        int v = wsum[lane];
        int wi = v;
        #pragma unroll
        for (int off = 1; off < 32; off <<= 1) {
            int t = __shfl_up_sync(0xFFFFFFFFu, wi, off);
            if (lane >= off) wi += t;
        }
        wsum[lane] = wi - v;
    }
    __syncthreads();

    const int offset = wsum[wid] + (inc - sum);

    #pragma unroll
    for (int q = 0; q < SCAN_PER; q++) {
        int i = base + q;
        if (i < N_NODES) {
            int excl = offset + excl_local[q];
            g_rowptr[i] = excl;
            g_cursor[i] = excl;
            int d = g_deg[i];
            g_dinv[i] = (d > 0) ? rsqrtf((float)d) : 0.0f;
        }
    }
    if (tid == 1023) g_rowptr[N_NODES] = offset + sum;
}

__global__ void k_fill(const int4* __restrict__ ei4) {
    int i = blockIdx.x * blockDim.x + threadIdx.x;
    if (i < E_EDGES / 4) {
        int4 r = ei4[i];
        int4 c = ei4[E_EDGES / 4 + i];
        int rr[4] = {r.x, r.y, r.z, r.w};
        int cc[4] = {c.x, c.y, c.z, c.w};
        #pragma unroll
        for (int q = 0; q < 4; q++) {
            int rv = min(max(rr[q], 0), N_NODES - 1);
            int cv = min(max(cc[q], 0), N_NODES - 1);
            int pos = atomicAdd(&g_cursor[rv], 1);
            if (pos >= 0 && pos < E_EDGES) g_col[pos] = cv;
        }
    }
}

// ---------------- bf16 hi/lo split conversion ----------------
__global__ void k_cvt(const float4* __restrict__ src,
                      uint2* __restrict__ hi, uint2* __restrict__ lo, int n4) {
    int i = blockIdx.x * blockDim.x + threadIdx.x;
    if (i < n4) {
        float4 v = src[i];
        __nv_bfloat16 h[4], l[4];
        h[0] = __float2bfloat16_rn(v.x); l[0] = __float2bfloat16_rn(v.x - __bfloat162float(h[0]));
        h[1] = __float2bfloat16_rn(v.y); l[1] = __float2bfloat16_rn(v.y - __bfloat162float(h[1]));
        h[2] = __float2bfloat16_rn(v.z); l[2] = __float2bfloat16_rn(v.z - __bfloat162float(h[2]));
        h[3] = __float2bfloat16_rn(v.w); l[3] = __float2bfloat16_rn(v.w - __bfloat162float(h[3]));
        hi[i] = *reinterpret_cast<const uint2*>(h);
        lo[i] = *reinterpret_cast<const uint2*>(l);
    }
}

// ---------------- Tensor-core GEMM (bf16x3, mma.sync + ldmatrix + cp.async) ----------------
// out[n,o] = sum_k x[n,k]*W[o,k] + b[o]; also mir = fp16(out*dinv[n]).
// CTA tile 128x64, 8 warps (warp tile 32x32), 3-stage cp.async pipeline, k16 chunks.
// 3 segment MMAs per chunk: Ah*Wh + Al*Wh + Ah*Wl.
#define GBM 128
#define GBN 64
#define SMSTRIDE 24           // bf16 per smem row (16 data + 8 pad)
#define STG_B    18432        // stage bytes: (128+128+64+64)*24*2
#define OFF_AL   (128 * SMSTRIDE)
#define OFF_WH   (256 * SMSTRIDE)
#define OFF_WL   (320 * SMSTRIDE)
#define GEMM_SMEM (3 * STG_B) // 55296 bytes

__global__ __launch_bounds__(256) void k_gemm_mma(const float* __restrict__ bias,
                                                  float* __restrict__ out,
                                                  __half* __restrict__ mir) {
    extern __shared__ __nv_bfloat16 smem[];
    const uint32_t sbase = smem_u32(smem);

    const int tid  = threadIdx.x;
    const int wid  = tid >> 5;          // 0..7
    const int lane = tid & 31;
    const int bm   = blockIdx.x * GBM;
    const int bn   = blockIdx.y * GBN;
    const int wm   = (wid & 3) * 32;    // 0,32,64,96
    const int wn   = (wid >> 2) * 32;   // 0,32
    const int q    = lane >> 2;
    const int s    = lane & 3;

    // ldmatrix lane geometry
    const int lg   = lane >> 3;
    const int l8   = lane & 7;
    const int arow = l8 + ((lg & 1) << 3);
    const int acol = (lg >> 1) << 3;
    const int brow = l8 + ((lg >> 1) << 3);
    const int bcol = (lg & 1) << 3;

    const uint32_t aHiB = sbase + ((wm + arow) * SMSTRIDE + acol) * 2;
    const uint32_t aLoB = aHiB + OFF_AL * 2;
    const uint32_t bHiB = sbase + OFF_WH * 2 + ((wn + brow) * SMSTRIDE + bcol) * 2;
    const uint32_t bLoB = bHiB + (OFF_WL - OFF_WH) * 2;
    const int MI_B = 16 * SMSTRIDE * 2;   // 768 bytes per 16-row step

    // cp.async loader geometry: A = 256 x 16B chunks (1/thread, hi+lo);
    // W = 128 x 16B chunks (threads 0..127, hi+lo)
    const int ar = tid >> 1,  ak = (tid & 1) * 8;
    const int mv = (bm + ar < N_NODES) ? 16 : 0;
    const long ag = (long)min(bm + ar, N_NODES - 1) * IN_CH;
    const uint32_t dA = sbase + (ar * SMSTRIDE + ak) * 2;
    const int wr = tid >> 1,  wk = (tid & 1) * 8;   // valid for tid<128
    const long wg = (long)(bn + wr) * IN_CH;
    const uint32_t dW = sbase + OFF_WH * 2 + (wr * SMSTRIDE + wk) * 2;

    #define ISSUE(ch, stg)                                                       \
    {                                                                            \
        const int k0_ = (ch) * 16;                                               \
        const uint32_t so_ = (stg) * STG_B;                                      \
        CP_ASYNC16(dA + so_,              &g_xh[ag + k0_ + ak], mv);             \
        CP_ASYNC16(dA + so_ + OFF_AL * 2, &g_xl[ag + k0_ + ak], mv);             \
        if (tid < 128) {                                                         \
            CP_ASYNC16(dW + so_,                          &g_wh[wg + k0_ + wk], 16); \
            CP_ASYNC16(dW + so_ + (OFF_WL - OFF_WH) * 2,  &g_wl[wg + k0_ + wk], 16); \
        }                                                                        \
        CP_COMMIT();                                                             \
    }

    float d[2][4][4];
    #pragma unroll
    for (int mi = 0; mi < 2; mi++)
        #pragma unroll
        for (int ni = 0; ni < 4; ni++)
            #pragma unroll
            for (int r = 0; r < 4; r++) d[mi][ni][r] = 0.0f;

    const int NCHUNK = IN_CH / 16;   // 32
    ISSUE(0, 0);
    ISSUE(1, 1);

    for (int ch = 0; ch < NCHUNK; ch++) {
        CP_WAIT1();
        __syncthreads();   // stage ch%3 ready everywhere; all warps past compute(ch-1)

        if (ch + 2 < NCHUNK) ISSUE(ch + 2, (ch + 2) % 3);

        const uint32_t so = (ch % 3) * STG_B;

        unsigned ah[2][4], al[2][4], bh[4][2], bl[4][2];
        #pragma unroll
        for (int mi = 0; mi < 2; mi++) {
            LDSM_X4(ah[mi][0], ah[mi][1], ah[mi][2], ah[mi][3], aHiB + so + mi * MI_B);
            LDSM_X4(al[mi][0], al[mi][1], al[mi][2], al[mi][3], aLoB + so + mi * MI_B);
        }
        #pragma unroll
        for (int p = 0; p < 2; p++) {
            unsigned t0, t1, t2, t3;
            LDSM_X4(t0, t1, t2, t3, bHiB + so + p * MI_B);
            bh[2 * p][0] = t0; bh[2 * p][1] = t1;
            bh[2 * p + 1][0] = t2; bh[2 * p + 1][1] = t3;
            LDSM_X4(t0, t1, t2, t3, bLoB + so + p * MI_B);
            bl[2 * p][0] = t0; bl[2 * p][1] = t1;
            bl[2 * p + 1][0] = t2; bl[2 * p + 1][1] = t3;
        }

        #pragma unroll
        for (int mi = 0; mi < 2; mi++) {
            #pragma unroll
            for (int ni = 0; ni < 4; ni++) MMA_BF16(d[mi][ni], ah[mi], bh[ni][0], bh[ni][1]);
            #pragma unroll
            for (int ni = 0; ni < 4; ni++) MMA_BF16(d[mi][ni], al[mi], bh[ni][0], bh[ni][1]);
            #pragma unroll
            for (int ni = 0; ni < 4; ni++) MMA_BF16(d[mi][ni], ah[mi], bl[ni][0], bl[ni][1]);
        }
    }
    #undef ISSUE

    // ---- epilogue: bias, fp32 out, fp16 mirror (scaled by dinv) ----
    float2 bv[4];
    #pragma unroll
    for (int ni = 0; ni < 4; ni++) {
        int c = bn + wn + ni * 8 + s * 2;
        bv[ni].x = bias[c];
        bv[ni].y = bias[c + 1];
    }

    #pragma unroll
    for (int mi = 0; mi < 2; mi++) {
        int r0 = bm + wm + mi * 16 + q;
        int r1 = r0 + 8;
        float di0 = (r0 < N_NODES) ? g_dinv[r0] : 0.0f;
        float di1 = (r1 < N_NODES) ? g_dinv[r1] : 0.0f;
        #pragma unroll
        for (int ni = 0; ni < 4; ni++) {
            int c = bn + wn + ni * 8 + s * 2;
            if (r0 < N_NODES) {
                float o0 = d[mi][ni][0] + bv[ni].x;
                float o1 = d[mi][ni][1] + bv[ni].y;
                *reinterpret_cast<float2*>(&out[(long)r0 * OUT_CH + c]) = make_float2(o0, o1);
                *reinterpret_cast<__half2*>(&mir[(long)r0 * OUT_CH + c]) =
                    __floats2half2_rn(o0 * di0, o1 * di0);
            }
            if (r1 < N_NODES) {
                float o0 = d[mi][ni][2] + bv[ni].x;
                float o1 = d[mi][ni][3] + bv[ni].y;
                *reinterpret_cast<float2*>(&out[(long)r1 * OUT_CH + c]) = make_float2(o0, o1);
                *reinterpret_cast<__half2*>(&mir[(long)r1 * OUT_CH + c]) =
                    __floats2half2_rn(o0 * di1, o1 * di1);
            }
        }
    }
}

// ---------------- SpMM gather: one row per 64-thread block ----------------
__global__ __launch_bounds__(64) void k_spmm(const uint2* __restrict__ h16,
                                             const float4* __restrict__ base4,
                                             const float* __restrict__ wptr,
                                             int widx,
                                             float4* __restrict__ out4,
                                             uint2* __restrict__ mir) {
    __shared__ int scol[256];

    const int row = blockIdx.x;
    const int tid = threadIdx.x;        // 0..63, owns 4 channels
    const int s   = g_rowptr[row];
    const int e   = g_rowptr[row + 1];

    float4 acc = make_float4(0.f, 0.f, 0.f, 0.f);

    for (int bs = s; bs < e; bs += 256) {
        int cnt = min(256, e - bs);
        for (int j = tid; j < cnt; j += 64) scol[j] = g_col[bs + j];
        __syncthreads();
        int j = 0;
        for (; j + 4 <= cnt; j += 4) {
            int c0 = scol[j + 0], c1 = scol[j + 1], c2 = scol[j + 2], c3 = scol[j + 3];
            uint2 u0 = h16[(long)c0 * 64 + tid];
            uint2 u1 = h16[(long)c1 * 64 + tid];
            uint2 u2 = h16[(long)c2 * 64 + tid];
            uint2 u3 = h16[(long)c3 * 64 + tid];
            float2 a0 = __half22float2(*reinterpret_cast<const __half2*>(&u0.x));
            float2 b0 = __half22float2(*reinterpret_cast<const __half2*>(&u0.y));
            float2 a1 = __half22float2(*reinterpret_cast<const __half2*>(&u1.x));
            float2 b1 = __half22float2(*reinterpret_cast<const __half2*>(&u1.y));
            float2 a2 = __half22float2(*reinterpret_cast<const __half2*>(&u2.x));
            float2 b2 = __half22float2(*reinterpret_cast<const __half2*>(&u2.y));
            float2 a3 = __half22float2(*reinterpret_cast<const __half2*>(&u3.x));
            float2 b3 = __half22float2(*reinterpret_cast<const __half2*>(&u3.y));
            acc.x += a0.x + a1.x + a2.x + a3.x;
            acc.y += a0.y + a1.y + a2.y + a3.y;
            acc.z += b0.x + b1.x + b2.x + b3.x;
            acc.w += b0.y + b1.y + b2.y + b3.y;
        }
        for (; j < cnt; j++) {
            uint2 u = h16[(long)scol[j] * 64 + tid];
            float2 a = __half22float2(*reinterpret_cast<const __half2*>(&u.x));
            float2 b = __half22float2(*reinterpret_cast<const __half2*>(&u.y));
            acc.x += a.x; acc.y += a.y; acc.z += b.x; acc.w += b.y;
        }
        __syncthreads();
    }

    const float di = g_dinv[row];
    float4 r;
    r.x = di * acc.x; r.y = di * acc.y; r.z = di * acc.z; r.w = di * acc.w;

    float4 o;
    if (base4 != nullptr) {
        float wk = wptr[widx];
        float4 bv = base4[(long)row * 64 + tid];
        o.x = bv.x + wk * r.x;
        o.y = bv.y + wk * r.y;
        o.z = bv.z + wk * r.z;
        o.w = bv.w + wk * r.w;
    } else {
        o = r;
    }
    if (out4 != nullptr) out4[(long)row * 64 + tid] = o;
    if (mir != nullptr) {
        __half h[4];
        h[0] = __float2half(o.x * di);
        h[1] = __float2half(o.y * di);
        h[2] = __float2half(o.z * di);
        h[3] = __float2half(o.w * di);
        mir[(long)row * 64 + tid] = *reinterpret_cast<const uint2*>(h);
    }
}

// ---------------- launch ----------------
extern "C" void kernel_launch(void* const* d_in, const int* in_sizes, int n_in,
                              void* d_out, int out_size) {
    const float* x   = (const float*)d_in[0];
    const int*   ei  = (const int*)d_in[1];      // edge_index delivered as int32
    const float* lw  = (const float*)d_in[2];
    const float* lb  = (const float*)d_in[3];
    const float* wts = (const float*)d_in[4];
    float*       out = (float*)d_out;

    float* bufB;  __half *m0, *m1, *m2;
    __nv_bfloat16 *xh, *xl, *wh, *wl;
    int* degp;
    cudaGetSymbolAddress((void**)&bufB, g_bufB);
    cudaGetSymbolAddress((void**)&m0, g_m0);
    cudaGetSymbolAddress((void**)&m1, g_m1);
    cudaGetSymbolAddress((void**)&m2, g_m2);
    cudaGetSymbolAddress((void**)&xh, g_xh);
    cudaGetSymbolAddress((void**)&xl, g_xl);
    cudaGetSymbolAddress((void**)&wh, g_wh);
    cudaGetSymbolAddress((void**)&wl, g_wl);
    cudaGetSymbolAddress((void**)&degp, g_deg);

    // one-time infra (created on the non-capturing correctness call)
    static cudaStream_t s2 = nullptr;
    static cudaEvent_t evStart, evScan, evCvt, evFill;
    if (s2 == nullptr) {
        cudaStreamCreateWithFlags(&s2, cudaStreamNonBlocking);
        cudaEventCreateWithFlags(&evStart, cudaEventDisableTiming);
        cudaEventCreateWithFlags(&evScan,  cudaEventDisableTiming);
        cudaEventCreateWithFlags(&evCvt,   cudaEventDisableTiming);
        cudaEventCreateWithFlags(&evFill,  cudaEventDisableTiming);
        cudaFuncSetAttribute(k_gemm_mma, cudaFuncAttributeMaxDynamicSharedMemorySize, GEMM_SMEM);
    }

    // fork side stream from the main (captured) stream
    cudaEventRecord(evStart, 0);
    cudaStreamWaitEvent(s2, evStart, 0);

    // main stream: CSR degree + scan (produces dinv + cursor)
    cudaMemsetAsync(degp, 0, N_NODES * sizeof(int), 0);
    k_count<<<CNT_BLOCKS, 256>>>((const int4*)ei);
    k_scan<<<1, 1024>>>();
    cudaEventRecord(evScan, 0);

    // side stream: bf16 splits (independent), then fill (needs scan's cursor)
    {
        int n4 = (N_NODES * IN_CH) / 4;
        k_cvt<<<(n4 + 255) / 256, 256, 0, s2>>>((const float4*)x, (uint2*)xh, (uint2*)xl, n4);
        int w4 = (OUT_CH * IN_CH) / 4;
        k_cvt<<<(w4 + 255) / 256, 256, 0, s2>>>((const float4*)lw, (uint2*)wh, (uint2*)wl, w4);
    }
    cudaEventRecord(evCvt, s2);
    cudaStreamWaitEvent(s2, evScan, 0);
    k_fill<<<(E_EDGES / 4 + 255) / 256, 256, 0, s2>>>((const int4*)ei);
    cudaEventRecord(evFill, s2);

    // main stream: GEMM (needs cvt + scan); fill overlaps with it on s2
    cudaStreamWaitEvent(0, evCvt, 0);
    dim3 ggrid((N_NODES + GBM - 1) / GBM, OUT_CH / GBN);
    k_gemm_mma<<<ggrid, 256, GEMM_SMEM>>>(lb, out, m0);

    // join fill before SpMM chain
    cudaStreamWaitEvent(0, evFill, 0);

    // k=0: bufB = out0 + w0 * A(out0); m1 = fp16(bufB * dinv)
    k_spmm<<<N_NODES, 64>>>((const uint2*)m0, (const float4*)out, wts, 0,
                            (float4*)bufB, (uint2*)m1);
    // k=1 hop 1: m2 = fp16(A(bufB) * dinv)   (fp32 output not needed)
    k_spmm<<<N_NODES, 64>>>((const uint2*)m1, nullptr, wts, 0,
                            nullptr, (uint2*)m2);
    // k=1 hop 2: d_out = bufB + w1 * A(prev)
    k_spmm<<<N_NODES, 64>>>((const uint2*)m2, (const float4*)bufB, wts, 1,
                            (float4*)out, nullptr);
}